// round 11
// baseline (speedup 1.0000x reference)
#include <cuda_runtime.h>
#include <cuda_bf16.h>
#include <stdint.h>
#include <math.h>

#define NB 4
#define NC 128
#define NP 128
#define ND 128
#define NG 512
#define NROW (NB * NC * NP)            // 65536
#define NELEM ((size_t)NROW * ND)      // 8388608

typedef unsigned long long u64;

#define SA 136                         // bf16 stride for mma tiles
#define TILE_U16 (128 * SA)            // 17408 uint16 per tile
#define OFF32 (NROW * 64)              // u32 per split buffer

// -------------------- scratch --------------------
__device__ float g_qzn[NELEM];
__device__ float g_xacc[NELEM];

// packed bf16x2 (hi/lo split) buffers
__device__ uint32_t g_qh[OFF32], g_ql[OFF32];                  // qzn split
__device__ uint32_t g_sph[4 * OFF32], g_spl[4 * OFF32];        // tu/tv/cu/cv outputs split
__device__ uint32_t g_wh[4 * 4 * 8192], g_wl[4 * 4 * 8192];    // attention weights
__device__ uint32_t g_tnh[4 * 512 * 64], g_tnl[4 * 512 * 64];  // topic natural
__device__ uint32_t g_tth[4 * 4 * 8192], g_ttl[4 * 4 * 8192];  // topic transposed
__device__ uint32_t g_w1h[8192], g_w1l[8192];
__device__ uint32_t g_w2h[8192], g_w2l[8192];

// -------------------- bf16 split + mma.sync helpers --------------------
__device__ __forceinline__ uint32_t pkbf(__nv_bfloat16 a, __nv_bfloat16 b) {
    return (uint32_t)__bfloat16_as_ushort(a) | ((uint32_t)__bfloat16_as_ushort(b) << 16);
}
__device__ __forceinline__ void split2(float x0, float x1, uint32_t &hi, uint32_t &lo) {
    __nv_bfloat16 h0 = __float2bfloat16(x0), h1 = __float2bfloat16(x1);
    hi = pkbf(h0, h1);
    lo = pkbf(__float2bfloat16(x0 - __bfloat162float(h0)),
              __float2bfloat16(x1 - __bfloat162float(h1)));
}

__device__ __forceinline__ void mma_bf16(float* c, const uint32_t* a, const uint32_t* b) {
    asm volatile(
        "mma.sync.aligned.m16n8k16.row.col.f32.bf16.bf16.f32 "
        "{%0,%1,%2,%3}, {%4,%5,%6,%7}, {%8,%9}, {%0,%1,%2,%3};"
        : "+f"(c[0]), "+f"(c[1]), "+f"(c[2]), "+f"(c[3])
        : "r"(a[0]), "r"(a[1]), "r"(a[2]), "r"(a[3]), "r"(b[0]), "r"(b[1]));
}

__device__ __forceinline__ void lda(const uint16_t* A, int r, int k, uint32_t* f) {
    const uint16_t* p = A + r * SA + k;
    f[0] = *(const uint32_t*)p;
    f[1] = *(const uint32_t*)(p + 8 * SA);
    f[2] = *(const uint32_t*)(p + 8);
    f[3] = *(const uint32_t*)(p + 8 * SA + 8);
}
__device__ __forceinline__ void ldb(const uint16_t* B, int n, int k, uint32_t* f) {
    const uint16_t* p = B + n * SA + k;
    f[0] = *(const uint32_t*)p;
    f[1] = *(const uint32_t*)(p + 8);
}

// copy packed-u32 contiguous global tile [128][64] into smem u16 tile
__device__ __forceinline__ void copy_tile(const uint32_t* __restrict__ srch,
                                          const uint32_t* __restrict__ srcl,
                                          uint16_t* Ah, uint16_t* Al,
                                          int tid, int nthr) {
    const u64* sh = (const u64*)srch;
    const u64* sl = (const u64*)srcl;
    for (int i = tid; i < 4096; i += nthr) {
        int r = i >> 5, c4 = (i & 31) * 4;
        *(u64*)(Ah + r * SA + c4) = sh[i];
        *(u64*)(Al + r * SA + c4) = sl[i];
    }
}
__device__ __forceinline__ void copy_tile_strided(const uint32_t* __restrict__ srch,
                                                  const uint32_t* __restrict__ srcl,
                                                  size_t row_base, int row_stride,
                                                  uint16_t* Ah, uint16_t* Al,
                                                  int tid, int nthr) {
    for (int i = tid; i < 4096; i += nthr) {
        int r = i >> 5, j = i & 31;
        size_t s = (row_base + (size_t)r * row_stride) * 32 + j;
        *(u64*)(Ah + r * SA + j * 4) = ((const u64*)srch)[s];
        *(u64*)(Al + r * SA + j * 4) = ((const u64*)srcl)[s];
    }
}

// 3-term warp GEMM
template <int MT, int NT>
__device__ __forceinline__ void warp_gemm3(
    const uint16_t* Ah, const uint16_t* Al,
    const uint16_t* Bh, const uint16_t* Bl,
    int wm, int wn, int g, int t, float (&acc)[MT][NT][4]) {
#pragma unroll
    for (int kt = 0; kt < 8; kt++) {
        int k = kt * 16 + 2 * t;
        uint32_t bh[NT][2], bl[NT][2];
#pragma unroll
        for (int nt = 0; nt < NT; nt++) {
            int n = wn + nt * 8 + g;
            ldb(Bh, n, k, bh[nt]);
            ldb(Bl, n, k, bl[nt]);
        }
#pragma unroll
        for (int mt = 0; mt < MT; mt++) {
            uint32_t ah[4], al[4];
            int r = wm + mt * 16 + g;
            lda(Ah, r, k, ah);
            lda(Al, r, k, al);
#pragma unroll
            for (int nt = 0; nt < NT; nt++) {
                mma_bf16(acc[mt][nt], ah, bh[nt]);
                mma_bf16(acc[mt][nt], ah, bl[nt]);
                mma_bf16(acc[mt][nt], al, bh[nt]);
            }
        }
    }
}

// =====================================================================
// K0: prep — split all static weights once.
// =====================================================================
__global__ __launch_bounds__(256) void k_prep(
    const float* __restrict__ tuw, const float* __restrict__ tvw,
    const float* __restrict__ cuw, const float* __restrict__ cvw,
    const float* __restrict__ topic,
    const float* __restrict__ w1, const float* __restrict__ w2) {
    int tid = blockIdx.x * 256 + threadIdx.x;
    int nth = gridDim.x * 256;
    for (int i = tid; i < 4 * 4 * 8192; i += nth) {
        int which = i >> 15;
        int rem = i & 32767;
        const float* W = (which == 0 ? tuw : which == 1 ? tvw : which == 2 ? cuw : cvw);
        float2 v = *(const float2*)(W + (size_t)rem * 2);
        uint32_t hi, lo; split2(v.x, v.y, hi, lo);
        g_wh[i] = hi; g_wl[i] = lo;
    }
    for (int i = tid; i < 4 * 512 * 64; i += nth) {
        float2 v = *(const float2*)(topic + (size_t)i * 2);
        uint32_t hi, lo; split2(v.x, v.y, hi, lo);
        g_tnh[i] = hi; g_tnl[i] = lo;
    }
    for (int i = tid; i < 4 * 4 * 8192; i += nth) {
        int b = i >> 15;
        int gc = (i >> 13) & 3;
        int d = (i >> 6) & 127;
        int g2 = i & 63;
        int grow = gc * 128 + g2 * 2;
        float x0 = topic[((size_t)b * 512 + grow) * 128 + d];
        float x1 = topic[((size_t)b * 512 + grow + 1) * 128 + d];
        uint32_t hi, lo; split2(x0, x1, hi, lo);
        g_tth[i] = hi; g_ttl[i] = lo;
    }
    for (int i = tid; i < 8192; i += nth) {
        float2 v = *(const float2*)(w1 + (size_t)i * 2);
        uint32_t hi, lo; split2(v.x, v.y, hi, lo);
        g_w1h[i] = hi; g_w1l[i] = lo;
        float2 u = *(const float2*)(w2 + (size_t)i * 2);
        split2(u.x, u.y, hi, lo);
        g_w2h[i] = hi; g_w2l[i] = lo;
    }
}

// =====================================================================
// K1: qzn = LN(qz) (fp32 + split); xacc = 0.5*(qz + unary).
// =====================================================================
__global__ __launch_bounds__(256) void k_ln_init(
    const float* __restrict__ qz, const float* __restrict__ unary,
    const float* __restrict__ gamma, const float* __restrict__ beta) {
    int row = blockIdx.x * 8 + (threadIdx.x >> 5);
    int lane = threadIdx.x & 31;
    size_t base = (size_t)row * 128 + lane * 4;
    float4 v = *(const float4*)(qz + base);
    float s = v.x + v.y + v.z + v.w;
    float ss = v.x * v.x + v.y * v.y + v.z * v.z + v.w * v.w;
#pragma unroll
    for (int o = 16; o > 0; o >>= 1) {
        s += __shfl_xor_sync(0xffffffffu, s, o);
        ss += __shfl_xor_sync(0xffffffffu, ss, o);
    }
    float m = s * (1.0f / 128.0f);
    float var = ss * (1.0f / 128.0f) - m * m;
    float inv = rsqrtf(var + 1e-5f);
    float4 u = *(const float4*)(unary + base);
    float4 g4 = *(const float4*)(gamma + lane * 4);
    float4 b4 = *(const float4*)(beta + lane * 4);
    float4 qn, xa;
    qn.x = (v.x - m) * inv * g4.x + b4.x;
    qn.y = (v.y - m) * inv * g4.y + b4.y;
    qn.z = (v.z - m) * inv * g4.z + b4.z;
    qn.w = (v.w - m) * inv * g4.w + b4.w;
    xa.x = 0.5f * (v.x + u.x);
    xa.y = 0.5f * (v.y + u.y);
    xa.z = 0.5f * (v.z + u.z);
    xa.w = 0.5f * (v.w + u.w);
    *(float4*)(g_qzn + base) = qn;
    *(float4*)(g_xacc + base) = xa;
    uint32_t hi, lo;
    split2(qn.x, qn.y, hi, lo);
    g_qh[row * 64 + lane * 2] = hi;
    g_ql[row * 64 + lane * 2] = lo;
    split2(qn.z, qn.w, hi, lo);
    g_qh[row * 64 + lane * 2 + 1] = hi;
    g_ql[row * 64 + lane * 2 + 1] = lo;
}

// =====================================================================
// K2 (mma): 4 batched linears -> split outputs. 1024 thr, 32 warps m16n32.
// =====================================================================
__global__ __launch_bounds__(1024) void k_gemm4() {
    extern __shared__ uint16_t smu[];
    uint16_t* Ah = smu;
    uint16_t* Al = Ah + TILE_U16;
    uint16_t* Bh = Al + TILE_U16;
    uint16_t* Bl = Bh + TILE_U16;
    int tid = threadIdx.x, lane = tid & 31, w = tid >> 5;
    int g = lane >> 2, t = lane & 3;
    int row0 = blockIdx.x * 128;
    int b = row0 >> 14;
    int which = blockIdx.y;
    int woff = which * 32768 + b * 8192;
    uint32_t* Oh = g_sph + (size_t)which * OFF32;
    uint32_t* Ol = g_spl + (size_t)which * OFF32;

    copy_tile(g_qh + (size_t)row0 * 64, g_ql + (size_t)row0 * 64, Ah, Al, tid, 1024);
    copy_tile(g_wh + woff, g_wl + woff, Bh, Bl, tid, 1024);
    __syncthreads();

    int wm = (w >> 2) * 16, wn = (w & 3) * 32;
    float acc[1][4][4] = {};
    warp_gemm3<1, 4>(Ah, Al, Bh, Bl, wm, wn, g, t, acc);

#pragma unroll
    for (int nt = 0; nt < 4; nt++) {
        int row = row0 + wm + g;
        int col = wn + nt * 8 + 2 * t;
        uint32_t hi, lo;
        split2(acc[0][nt][0], acc[0][nt][1], hi, lo);
        Oh[(size_t)row * 64 + col / 2] = hi;
        Ol[(size_t)row * 64 + col / 2] = lo;
        split2(acc[0][nt][2], acc[0][nt][3], hi, lo);
        Oh[(size_t)(row + 8) * 64 + col / 2] = hi;
        Ol[(size_t)(row + 8) * 64 + col / 2] = lo;
    }
}

// =====================================================================
// attention score core (512-thr shape): per-head mma + max-free softmax.
// warp = (wp m-tile 0..7, half q-half 0..1). probs[8][4] = (1/16)*softmax.
// sumbuf: [8][128][2] floats (8KB).
// =====================================================================
__device__ __forceinline__ void attn_probs(const uint16_t* Uh, const uint16_t* Ul,
                                           const uint16_t* Vh, const uint16_t* Vl,
                                           float* sumbuf, int wp, int half,
                                           int g, int t, float (&probs)[8][4]) {
#pragma unroll
    for (int nt = 0; nt < 8; nt++)
#pragma unroll
        for (int c = 0; c < 4; c++) probs[nt][c] = 0.0f;

    int row0 = wp * 16 + g;
    for (int h = 0; h < 8; h++) {
        int k = h * 16 + 2 * t;
        uint32_t ah[4], al[4];
        lda(Uh, row0, k, ah);
        lda(Ul, row0, k, al);
        float sacc[8][4];
#pragma unroll
        for (int nt = 0; nt < 8; nt++) {
#pragma unroll
            for (int c = 0; c < 4; c++) sacc[nt][c] = 0.0f;
            int n = half * 64 + nt * 8 + g;
            uint32_t bh[2], bl[2];
            ldb(Vh, n, k, bh);
            ldb(Vl, n, k, bl);
            mma_bf16(sacc[nt], ah, bh);
            mma_bf16(sacc[nt], ah, bl);
            mma_bf16(sacc[nt], al, bh);
        }
        float s0 = 0.0f, s1 = 0.0f;
#pragma unroll
        for (int nt = 0; nt < 8; nt++) {
            sacc[nt][0] = __expf(0.25f * sacc[nt][0]);
            sacc[nt][1] = __expf(0.25f * sacc[nt][1]);
            sacc[nt][2] = __expf(0.25f * sacc[nt][2]);
            sacc[nt][3] = __expf(0.25f * sacc[nt][3]);
            s0 += sacc[nt][0] + sacc[nt][1];
            s1 += sacc[nt][2] + sacc[nt][3];
        }
        s0 += __shfl_xor_sync(0xffffffffu, s0, 1);
        s0 += __shfl_xor_sync(0xffffffffu, s0, 2);
        s1 += __shfl_xor_sync(0xffffffffu, s1, 1);
        s1 += __shfl_xor_sync(0xffffffffu, s1, 2);
        if (t == 0) {
            sumbuf[(h * 128 + row0) * 2 + half] = s0;
            sumbuf[(h * 128 + row0 + 8) * 2 + half] = s1;
        }
        __syncthreads();
        float inv0 = 1.0f / (16.0f * (sumbuf[(h * 128 + row0) * 2] +
                                      sumbuf[(h * 128 + row0) * 2 + 1]));
        float inv1 = 1.0f / (16.0f * (sumbuf[(h * 128 + row0 + 8) * 2] +
                                      sumbuf[(h * 128 + row0 + 8) * 2 + 1]));
#pragma unroll
        for (int nt = 0; nt < 8; nt++) {
            probs[nt][0] = fmaf(sacc[nt][0], inv0, probs[nt][0]);
            probs[nt][1] = fmaf(sacc[nt][1], inv0, probs[nt][1]);
            probs[nt][2] = fmaf(sacc[nt][2], inv1, probs[nt][2]);
            probs[nt][3] = fmaf(sacc[nt][3], inv1, probs[nt][3]);
        }
    }
}

// =====================================================================
// K3: time attention. block=(b,c), 512 thr.
// scores mma -> probs to smem (aliases V) -> PV mma, no atomics.
// =====================================================================
__global__ __launch_bounds__(512) void k_time_attn() {
    extern __shared__ uint16_t smu[];
    uint16_t* Uh = smu;
    uint16_t* Ul = Uh + TILE_U16;
    uint16_t* Vh = Ul + TILE_U16;
    uint16_t* Vl = Vh + TILE_U16;
    float* sumbuf = (float*)(Vl + TILE_U16);     // 8KB
    // phase-2 aliases
    uint16_t* Qth = Uh;                           // qzn^T split (d-major)
    uint16_t* Qtl = Ul;
    uint16_t* Ph = Vh;                            // probs split (p rows, q cols)
    uint16_t* Pl = Vl;

    int tid = threadIdx.x, lane = tid & 31, w = tid >> 5;
    int g = lane >> 2, t = lane & 3;
    int wp = w & 7, half = w >> 3;
    int bid = blockIdx.x;
    size_t base = (size_t)bid * 16384;

    copy_tile(g_sph + (size_t)bid * 8192, g_spl + (size_t)bid * 8192, Uh, Ul, tid, 512);
    copy_tile(g_sph + OFF32 + (size_t)bid * 8192, g_spl + OFF32 + (size_t)bid * 8192,
              Vh, Vl, tid, 512);
    __syncthreads();

    float probs[8][4];
    attn_probs(Uh, Ul, Vh, Vl, sumbuf, wp, half, g, t, probs);
    __syncthreads();   // all U/V reads done

    // probs -> Ph/Pl (split), rows=p, cols=q
    int prow = wp * 16 + g;
#pragma unroll
    for (int nt = 0; nt < 8; nt++) {
        int col = half * 64 + nt * 8 + 2 * t;
        uint32_t hi, lo;
        split2(probs[nt][0], probs[nt][1], hi, lo);
        *(uint32_t*)(Ph + prow * SA + col) = hi;
        *(uint32_t*)(Pl + prow * SA + col) = lo;
        split2(probs[nt][2], probs[nt][3], hi, lo);
        *(uint32_t*)(Ph + (prow + 8) * SA + col) = hi;
        *(uint32_t*)(Pl + (prow + 8) * SA + col) = lo;
    }
    // qzn^T split directly from global (coalesced along d)
    for (int i = tid; i < 8192; i += 512) {
        int d = i & 127, j = i >> 7;
        float x0 = g_qzn[base + (size_t)(2 * j) * 128 + d];
        float x1 = g_qzn[base + (size_t)(2 * j + 1) * 128 + d];
        uint32_t hi, lo; split2(x0, x1, hi, lo);
        *(uint32_t*)(Qth + d * SA + 2 * j) = hi;
        *(uint32_t*)(Qtl + d * SA + 2 * j) = lo;
    }
    __syncthreads();

    // PV: m[p][d] = sum_q P[p][q] Qn[q][d]. warp owns (wp, d-half) -> unique.
    float accp[8][4] = {};
#pragma unroll
    for (int kt = 0; kt < 8; kt++) {
        int k = kt * 16 + 2 * t;
        uint32_t ah[4], al[4];
        lda(Ph, prow, k, ah);
        lda(Pl, prow, k, al);
#pragma unroll
        for (int nt = 0; nt < 8; nt++) {
            int n = half * 64 + nt * 8 + g;
            uint32_t bh[2], bl[2];
            ldb(Qth, n, k, bh);
            ldb(Qtl, n, k, bl);
            mma_bf16(accp[nt], ah, bh);
            mma_bf16(accp[nt], ah, bl);
            mma_bf16(accp[nt], al, bh);
        }
    }
#pragma unroll
    for (int nt = 0; nt < 8; nt++) {
        int col = half * 64 + nt * 8 + 2 * t;
        size_t g0 = base + (size_t)prow * 128 + col;
        size_t g1 = base + (size_t)(prow + 8) * 128 + col;
        float2 x0 = *(const float2*)(g_xacc + g0);
        float2 x1 = *(const float2*)(g_xacc + g1);
        x0.x += accp[nt][0];
        x0.y += accp[nt][1];
        x1.x += accp[nt][2];
        x1.y += accp[nt][3];
        *(float2*)(g_xacc + g0) = x0;
        *(float2*)(g_xacc + g1) = x1;
    }
}

// =====================================================================
// K4: channel attention. block=(b,p), 512 thr. scores mma + elementwise.
// =====================================================================
__global__ __launch_bounds__(512) void k_chan_attn() {
    extern __shared__ uint16_t smu[];
    uint16_t* Uh = smu;
    uint16_t* Ul = Uh + TILE_U16;
    uint16_t* Vh = Ul + TILE_U16;
    uint16_t* Vl = Vh + TILE_U16;
    float* sumbuf = (float*)(Vl + TILE_U16);

    int tid = threadIdx.x, lane = tid & 31, w = tid >> 5;
    int g = lane >> 2, t = lane & 3;
    int wp = w & 7, half = w >> 3;
    int bp = blockIdx.x;
    int b = bp >> 7, p = bp & 127;
    size_t rowbase = (size_t)b * 16384 + p;
    size_t bbase = (size_t)b * 2097152 + (size_t)p * 128;

    copy_tile_strided(g_sph + 2 * (size_t)OFF32, g_spl + 2 * (size_t)OFF32,
                      rowbase, 128, Uh, Ul, tid, 512);
    copy_tile_strided(g_sph + 3 * (size_t)OFF32, g_spl + 3 * (size_t)OFF32,
                      rowbase, 128, Vh, Vl, tid, 512);
    __syncthreads();

    float probs[8][4];
    attn_probs(Uh, Ul, Vh, Vl, sumbuf, wp, half, g, t, probs);

    int c0 = wp * 16 + g;
#pragma unroll
    for (int nt = 0; nt < 8; nt++) {
        int col = half * 64 + nt * 8 + 2 * t;
        size_t g0 = bbase + (size_t)c0 * 16384 + col;
        size_t g1 = bbase + (size_t)(c0 + 8) * 16384 + col;
        float2 q0 = *(const float2*)(g_qzn + g0);
        float2 q1 = *(const float2*)(g_qzn + g1);
        float2 x0 = *(const float2*)(g_xacc + g0);
        float2 x1 = *(const float2*)(g_xacc + g1);
        x0.x += probs[nt][0] * q0.x;
        x0.y += probs[nt][1] * q0.y;
        x1.x += probs[nt][2] * q1.x;
        x1.y += probs[nt][3] * q1.y;
        *(float2*)(g_xacc + g0) = x0;
        *(float2*)(g_xacc + g1) = x1;
    }
}

// =====================================================================
// K5 (mma): topic. 128 rows/block, 1024 thr, 32 warps m16n32, 512 blocks.
// =====================================================================
__global__ __launch_bounds__(1024) void k_topic() {
    extern __shared__ uint16_t smu[];
    uint16_t* Qh = smu;
    uint16_t* Ql = Qh + TILE_U16;
    uint16_t* Bh = Ql + TILE_U16;
    uint16_t* Bl = Bh + TILE_U16;
    uint16_t* Sh = Bl + TILE_U16;
    uint16_t* Sl = Sh + TILE_U16;
    float* rs = (float*)(Sl + TILE_U16);
    int tid = threadIdx.x, lane = tid & 31, w = tid >> 5;
    int g = lane >> 2, t = lane & 3;
    int wm = (w >> 2) * 16, wn = (w & 3) * 32;
    int row0 = blockIdx.x * 128;
    int b = row0 >> 14;

    copy_tile(g_qh + (size_t)row0 * 64, g_ql + (size_t)row0 * 64, Qh, Ql, tid, 1024);
    if (tid < 128) rs[tid] = 0.0f;

    float macc[1][4][4] = {};

    for (int gc = 0; gc < 4; gc++) {
        int noff = b * 32768 + gc * 8192;
        __syncthreads();
        copy_tile(g_tnh + noff, g_tnl + noff, Bh, Bl, tid, 1024);
        __syncthreads();

        float sacc[1][4][4] = {};
        warp_gemm3<1, 4>(Qh, Ql, Bh, Bl, wm, wn, g, t, sacc);
        __syncthreads();

        int row = wm + g;
        float p0 = 0.f, p1 = 0.f;
#pragma unroll
        for (int nt = 0; nt < 4; nt++) {
            float r0 = fmaxf(sacc[0][nt][0], 0.f);
            float r1 = fmaxf(sacc[0][nt][1], 0.f);
            float r2 = fmaxf(sacc[0][nt][2], 0.f);
            float r3 = fmaxf(sacc[0][nt][3], 0.f);
            p0 += r0 + r1;
            p1 += r2 + r3;
            int col = wn + nt * 8 + 2 * t;
            uint32_t hi, lo;
            split2(r0, r1, hi, lo);
            *(uint32_t*)(Sh + row * SA + col) = hi;
            *(uint32_t*)(Sl + row * SA + col) = lo;
            split2(r2, r3, hi, lo);
            *(uint32_t*)(Sh + (row + 8) * SA + col) = hi;
            *(uint32_t*)(Sl + (row + 8) * SA + col) = lo;
        }
        p0 += __shfl_xor_sync(0xffffffffu, p0, 1);
        p0 += __shfl_xor_sync(0xffffffffu, p0, 2);
        p1 += __shfl_xor_sync(0xffffffffu, p1, 1);
        p1 += __shfl_xor_sync(0xffffffffu, p1, 2);
        if (t == 0) {
            atomicAdd(rs + row, p0);
            atomicAdd(rs + row + 8, p1);
        }
        copy_tile(g_tth + noff, g_ttl + noff, Bh, Bl, tid, 1024);
        __syncthreads();

        warp_gemm3<1, 4>(Sh, Sl, Bh, Bl, wm, wn, g, t, macc);
    }
    __syncthreads();

    int row = wm + g;
    float idn0 = 0.5f / fmaxf(rs[row], 1e-6f);
    float idn1 = 0.5f / fmaxf(rs[row + 8], 1e-6f);
#pragma unroll
    for (int nt = 0; nt < 4; nt++) {
        int col = wn + nt * 8 + 2 * t;
        size_t g0 = (size_t)(row0 + row) * 128 + col;
        size_t g1 = (size_t)(row0 + row + 8) * 128 + col;
        float2 x0 = *(float2*)(g_xacc + g0);
        float2 x1 = *(float2*)(g_xacc + g1);
        x0.x += macc[0][nt][0] * idn0;
        x0.y += macc[0][nt][1] * idn0;
        x1.x += macc[0][nt][2] * idn1;
        x1.y += macc[0][nt][3] * idn1;
        *(float2*)(g_xacc + g0) = x0;
        *(float2*)(g_xacc + g1) = x1;
    }
}

// =====================================================================
// K6 (mma): mlp. 128 rows/block, 1024 thr, 32 warps m16n32.
// =====================================================================
__global__ __launch_bounds__(1024) void k_mlp(
    const float* __restrict__ gamma, const float* __restrict__ beta,
    const float* __restrict__ b1, const float* __restrict__ b2,
    float* __restrict__ out) {
    extern __shared__ uint16_t smu[];
    uint16_t* Ah = smu;
    uint16_t* Al = Ah + TILE_U16;
    uint16_t* Bh = Al + TILE_U16;
    uint16_t* Bl = Bh + TILE_U16;
    int tid = threadIdx.x, lane = tid & 31, w = tid >> 5;
    int g = lane >> 2, t = lane & 3;
    int row0 = blockIdx.x * 128;
    int wm = (w >> 2) * 16, wn = (w & 3) * 32;

    float4 g4 = *(const float4*)(gamma + lane * 4);
    float4 b4 = *(const float4*)(beta + lane * 4);
#pragma unroll
    for (int it = 0; it < 4; it++) {
        int r = w * 4 + it;
        size_t gb = (size_t)(row0 + r) * 128 + lane * 4;
        float4 v = *(const float4*)(g_xacc + gb);
        float s = v.x + v.y + v.z + v.w;
        float ss = v.x * v.x + v.y * v.y + v.z * v.z + v.w * v.w;
#pragma unroll
        for (int o = 16; o > 0; o >>= 1) {
            s += __shfl_xor_sync(0xffffffffu, s, o);
            ss += __shfl_xor_sync(0xffffffffu, ss, o);
        }
        float m = s * (1.0f / 128.0f);
        float var = ss * (1.0f / 128.0f) - m * m;
        float inv = rsqrtf(var + 1e-5f);
        float q0 = (v.x - m) * inv * g4.x + b4.x;
        float q1 = (v.y - m) * inv * g4.y + b4.y;
        float q2 = (v.z - m) * inv * g4.z + b4.z;
        float q3 = (v.w - m) * inv * g4.w + b4.w;
        uint32_t hi, lo;
        split2(q0, q1, hi, lo);
        *(uint32_t*)(Ah + r * SA + lane * 4) = hi;
        *(uint32_t*)(Al + r * SA + lane * 4) = lo;
        split2(q2, q3, hi, lo);
        *(uint32_t*)(Ah + r * SA + lane * 4 + 2) = hi;
        *(uint32_t*)(Al + r * SA + lane * 4 + 2) = lo;
    }
    copy_tile(g_w1h, g_w1l, Bh, Bl, tid, 1024);
    __syncthreads();

    float acc[1][4][4] = {};
    warp_gemm3<1, 4>(Ah, Al, Bh, Bl, wm, wn, g, t, acc);
    __syncthreads();

    int row = wm + g;
#pragma unroll
    for (int nt = 0; nt < 4; nt++) {
        int col = wn + nt * 8 + 2 * t;
        float bb0 = b1[col], bb1 = b1[col + 1];
        float x0 = acc[0][nt][0] + bb0, x1 = acc[0][nt][1] + bb1;
        float x2 = acc[0][nt][2] + bb0, x3 = acc[0][nt][3] + bb1;
        float gl0 = 0.5f * x0 * (1.0f + erff(x0 * 0.70710678118654752f));
        float gl1 = 0.5f * x1 * (1.0f + erff(x1 * 0.70710678118654752f));
        float gl2 = 0.5f * x2 * (1.0f + erff(x2 * 0.70710678118654752f));
        float gl3 = 0.5f * x3 * (1.0f + erff(x3 * 0.70710678118654752f));
        uint32_t hi, lo;
        split2(gl0, gl1, hi, lo);
        *(uint32_t*)(Ah + row * SA + col) = hi;
        *(uint32_t*)(Al + row * SA + col) = lo;
        split2(gl2, gl3, hi, lo);
        *(uint32_t*)(Ah + (row + 8) * SA + col) = hi;
        *(uint32_t*)(Al + (row + 8) * SA + col) = lo;
    }
    copy_tile(g_w2h, g_w2l, Bh, Bl, tid, 1024);
    __syncthreads();

    float acc2[1][4][4] = {};
    warp_gemm3<1, 4>(Ah, Al, Bh, Bl, wm, wn, g, t, acc2);

#pragma unroll
    for (int nt = 0; nt < 4; nt++) {
        int grow = row0 + wm + g;
        int col = wn + nt * 8 + 2 * t;
        float bb0 = b2[col], bb1 = b2[col + 1];
        size_t g0 = (size_t)grow * 128 + col;
        size_t g1 = (size_t)(grow + 8) * 128 + col;
        float2 x0 = *(const float2*)(g_xacc + g0);
        float2 x1 = *(const float2*)(g_xacc + g1);
        float2 o0 = {x0.x + acc2[0][nt][0] + bb0, x0.y + acc2[0][nt][1] + bb1};
        float2 o1 = {x1.x + acc2[0][nt][2] + bb0, x1.y + acc2[0][nt][3] + bb1};
        *(float2*)(out + g0) = o0;
        *(float2*)(out + g1) = o1;
    }
}

// =====================================================================
// launch
// =====================================================================
extern "C" void kernel_launch(void* const* d_in, const int* in_sizes, int n_in,
                              void* d_out, int out_size) {
    const float* qz    = (const float*)d_in[0];
    const float* unary = (const float*)d_in[1];
    const float* tuw   = (const float*)d_in[2];
    const float* tvw   = (const float*)d_in[3];
    const float* cuw   = (const float*)d_in[4];
    const float* cvw   = (const float*)d_in[5];
    const float* topic = (const float*)d_in[6];
    const float* gamma = (const float*)d_in[7];
    const float* beta  = (const float*)d_in[8];
    const float* w1    = (const float*)d_in[9];
    const float* b1    = (const float*)d_in[10];
    const float* w2    = (const float*)d_in[11];
    const float* b2    = (const float*)d_in[12];
    float* out = (float*)d_out;

    const int SMG = 4 * TILE_U16 * 2;                   // 139264
    const int SMA = 4 * TILE_U16 * 2 + 8192;            // 147456
    const int SMT = 6 * TILE_U16 * 2 + 512;             // 209408

    cudaFuncSetAttribute(k_gemm4, cudaFuncAttributeMaxDynamicSharedMemorySize, SMG);
    cudaFuncSetAttribute(k_time_attn, cudaFuncAttributeMaxDynamicSharedMemorySize, SMA);
    cudaFuncSetAttribute(k_chan_attn, cudaFuncAttributeMaxDynamicSharedMemorySize, SMA);
    cudaFuncSetAttribute(k_topic, cudaFuncAttributeMaxDynamicSharedMemorySize, SMT);
    cudaFuncSetAttribute(k_mlp, cudaFuncAttributeMaxDynamicSharedMemorySize, SMG);

    k_prep<<<256, 256>>>(tuw, tvw, cuw, cvw, topic, w1, w2);
    k_ln_init<<<NROW / 8, 256>>>(qz, unary, gamma, beta);
    k_gemm4<<<dim3(NROW / 128, 4), 1024, SMG>>>();
    k_time_attn<<<NB * NC, 512, SMA>>>();
    k_chan_attn<<<NB * NP, 512, SMA>>>();
    k_topic<<<NROW / 128, 1024, SMT>>>();
    k_mlp<<<NROW / 128, 1024, SMG>>>(gamma, beta, b1, b2, out);
}

// round 12
// speedup vs baseline: 1.0166x; 1.0166x over previous
#include <cuda_runtime.h>
#include <cuda_bf16.h>
#include <stdint.h>
#include <math.h>

#define NB 4
#define NC 128
#define NP 128
#define ND 128
#define NG 512
#define NROW (NB * NC * NP)            // 65536
#define NELEM ((size_t)NROW * ND)      // 8388608

typedef unsigned long long u64;

#define SA 136                         // bf16 stride for mma tiles
#define TILE_U16 (128 * SA)            // 17408 uint16 per tile
#define OFF32 (NROW * 64)              // u32 per split buffer

// -------------------- scratch --------------------
__device__ float g_qzn[NELEM];
__device__ float g_xacc[NELEM];

// packed bf16x2 (hi/lo split) buffers
__device__ uint32_t g_qh[OFF32], g_ql[OFF32];                  // qzn split
__device__ uint32_t g_sph[4 * OFF32], g_spl[4 * OFF32];        // tu/tv/cu/cv outputs split
__device__ uint32_t g_wh[4 * 4 * 8192], g_wl[4 * 4 * 8192];    // attention weights
__device__ uint32_t g_tnh[4 * 512 * 64], g_tnl[4 * 512 * 64];  // topic natural
__device__ uint32_t g_tth[4 * 4 * 8192], g_ttl[4 * 4 * 8192];  // topic transposed
__device__ uint32_t g_w1h[8192], g_w1l[8192];
__device__ uint32_t g_w2h[8192], g_w2l[8192];

// -------------------- helpers --------------------
__device__ __forceinline__ uint32_t pkbf(__nv_bfloat16 a, __nv_bfloat16 b) {
    return (uint32_t)__bfloat16_as_ushort(a) | ((uint32_t)__bfloat16_as_ushort(b) << 16);
}
__device__ __forceinline__ void split2(float x0, float x1, uint32_t &hi, uint32_t &lo) {
    __nv_bfloat16 h0 = __float2bfloat16(x0), h1 = __float2bfloat16(x1);
    hi = pkbf(h0, h1);
    lo = pkbf(__float2bfloat16(x0 - __bfloat162float(h0)),
              __float2bfloat16(x1 - __bfloat162float(h1)));
}

__device__ __forceinline__ void mma_bf16(float* c, const uint32_t* a, const uint32_t* b) {
    asm volatile(
        "mma.sync.aligned.m16n8k16.row.col.f32.bf16.bf16.f32 "
        "{%0,%1,%2,%3}, {%4,%5,%6,%7}, {%8,%9}, {%0,%1,%2,%3};"
        : "+f"(c[0]), "+f"(c[1]), "+f"(c[2]), "+f"(c[3])
        : "r"(a[0]), "r"(a[1]), "r"(a[2]), "r"(a[3]), "r"(b[0]), "r"(b[1]));
}

__device__ __forceinline__ void lda(const uint16_t* A, int r, int k, uint32_t* f) {
    const uint16_t* p = A + r * SA + k;
    f[0] = *(const uint32_t*)p;
    f[1] = *(const uint32_t*)(p + 8 * SA);
    f[2] = *(const uint32_t*)(p + 8);
    f[3] = *(const uint32_t*)(p + 8 * SA + 8);
}
__device__ __forceinline__ void ldb(const uint16_t* B, int n, int k, uint32_t* f) {
    const uint16_t* p = B + n * SA + k;
    f[0] = *(const uint32_t*)p;
    f[1] = *(const uint32_t*)(p + 8);
}

#define BAR2W(id) asm volatile("bar.sync %0, %1;" :: "r"(id), "r"(64) : "memory")

// copy packed-u32 contiguous global tile [128][64] into smem u16 tile
__device__ __forceinline__ void copy_tile(const uint32_t* __restrict__ srch,
                                          const uint32_t* __restrict__ srcl,
                                          uint16_t* Ah, uint16_t* Al,
                                          int tid, int nthr) {
    const u64* sh = (const u64*)srch;
    const u64* sl = (const u64*)srcl;
    for (int i = tid; i < 4096; i += nthr) {
        int r = i >> 5, c4 = (i & 31) * 4;
        *(u64*)(Ah + r * SA + c4) = sh[i];
        *(u64*)(Al + r * SA + c4) = sl[i];
    }
}
__device__ __forceinline__ void copy_tile_strided(const uint32_t* __restrict__ srch,
                                                  const uint32_t* __restrict__ srcl,
                                                  size_t row_base, int row_stride,
                                                  uint16_t* Ah, uint16_t* Al,
                                                  int tid, int nthr) {
    for (int i = tid; i < 4096; i += nthr) {
        int r = i >> 5, j = i & 31;
        size_t s = (row_base + (size_t)r * row_stride) * 32 + j;
        *(u64*)(Ah + r * SA + j * 4) = ((const u64*)srch)[s];
        *(u64*)(Al + r * SA + j * 4) = ((const u64*)srcl)[s];
    }
}

// 3-term warp GEMM
template <int MT, int NT>
__device__ __forceinline__ void warp_gemm3(
    const uint16_t* Ah, const uint16_t* Al,
    const uint16_t* Bh, const uint16_t* Bl,
    int wm, int wn, int g, int t, float (&acc)[MT][NT][4]) {
#pragma unroll
    for (int kt = 0; kt < 8; kt++) {
        int k = kt * 16 + 2 * t;
        uint32_t bh[NT][2], bl[NT][2];
#pragma unroll
        for (int nt = 0; nt < NT; nt++) {
            int n = wn + nt * 8 + g;
            ldb(Bh, n, k, bh[nt]);
            ldb(Bl, n, k, bl[nt]);
        }
#pragma unroll
        for (int mt = 0; mt < MT; mt++) {
            uint32_t ah[4], al[4];
            int r = wm + mt * 16 + g;
            lda(Ah, r, k, ah);
            lda(Al, r, k, al);
#pragma unroll
            for (int nt = 0; nt < NT; nt++) {
                mma_bf16(acc[mt][nt], ah, bh[nt]);
                mma_bf16(acc[mt][nt], ah, bl[nt]);
                mma_bf16(acc[mt][nt], al, bh[nt]);
            }
        }
    }
}

// =====================================================================
// K0: prep — split all static weights once.
// =====================================================================
__global__ __launch_bounds__(256) void k_prep(
    const float* __restrict__ tuw, const float* __restrict__ tvw,
    const float* __restrict__ cuw, const float* __restrict__ cvw,
    const float* __restrict__ topic,
    const float* __restrict__ w1, const float* __restrict__ w2) {
    int tid = blockIdx.x * 256 + threadIdx.x;
    int nth = gridDim.x * 256;
    for (int i = tid; i < 4 * 4 * 8192; i += nth) {
        int which = i >> 15;
        int rem = i & 32767;
        const float* W = (which == 0 ? tuw : which == 1 ? tvw : which == 2 ? cuw : cvw);
        float2 v = *(const float2*)(W + (size_t)rem * 2);
        uint32_t hi, lo; split2(v.x, v.y, hi, lo);
        g_wh[i] = hi; g_wl[i] = lo;
    }
    for (int i = tid; i < 4 * 512 * 64; i += nth) {
        float2 v = *(const float2*)(topic + (size_t)i * 2);
        uint32_t hi, lo; split2(v.x, v.y, hi, lo);
        g_tnh[i] = hi; g_tnl[i] = lo;
    }
    for (int i = tid; i < 4 * 4 * 8192; i += nth) {
        int b = i >> 15;
        int gc = (i >> 13) & 3;
        int d = (i >> 6) & 127;
        int g2 = i & 63;
        int grow = gc * 128 + g2 * 2;
        float x0 = topic[((size_t)b * 512 + grow) * 128 + d];
        float x1 = topic[((size_t)b * 512 + grow + 1) * 128 + d];
        uint32_t hi, lo; split2(x0, x1, hi, lo);
        g_tth[i] = hi; g_ttl[i] = lo;
    }
    for (int i = tid; i < 8192; i += nth) {
        float2 v = *(const float2*)(w1 + (size_t)i * 2);
        uint32_t hi, lo; split2(v.x, v.y, hi, lo);
        g_w1h[i] = hi; g_w1l[i] = lo;
        float2 u = *(const float2*)(w2 + (size_t)i * 2);
        split2(u.x, u.y, hi, lo);
        g_w2h[i] = hi; g_w2l[i] = lo;
    }
}

// =====================================================================
// K1: qzn = LN(qz) (fp32 + split); xacc = 0.5*(qz + unary).
// =====================================================================
__global__ __launch_bounds__(256) void k_ln_init(
    const float* __restrict__ qz, const float* __restrict__ unary,
    const float* __restrict__ gamma, const float* __restrict__ beta) {
    int row = blockIdx.x * 8 + (threadIdx.x >> 5);
    int lane = threadIdx.x & 31;
    size_t base = (size_t)row * 128 + lane * 4;
    float4 v = *(const float4*)(qz + base);
    float s = v.x + v.y + v.z + v.w;
    float ss = v.x * v.x + v.y * v.y + v.z * v.z + v.w * v.w;
#pragma unroll
    for (int o = 16; o > 0; o >>= 1) {
        s += __shfl_xor_sync(0xffffffffu, s, o);
        ss += __shfl_xor_sync(0xffffffffu, ss, o);
    }
    float m = s * (1.0f / 128.0f);
    float var = ss * (1.0f / 128.0f) - m * m;
    float inv = rsqrtf(var + 1e-5f);
    float4 u = *(const float4*)(unary + base);
    float4 g4 = *(const float4*)(gamma + lane * 4);
    float4 b4 = *(const float4*)(beta + lane * 4);
    float4 qn, xa;
    qn.x = (v.x - m) * inv * g4.x + b4.x;
    qn.y = (v.y - m) * inv * g4.y + b4.y;
    qn.z = (v.z - m) * inv * g4.z + b4.z;
    qn.w = (v.w - m) * inv * g4.w + b4.w;
    xa.x = 0.5f * (v.x + u.x);
    xa.y = 0.5f * (v.y + u.y);
    xa.z = 0.5f * (v.z + u.z);
    xa.w = 0.5f * (v.w + u.w);
    *(float4*)(g_qzn + base) = qn;
    *(float4*)(g_xacc + base) = xa;
    uint32_t hi, lo;
    split2(qn.x, qn.y, hi, lo);
    g_qh[row * 64 + lane * 2] = hi;
    g_ql[row * 64 + lane * 2] = lo;
    split2(qn.z, qn.w, hi, lo);
    g_qh[row * 64 + lane * 2 + 1] = hi;
    g_ql[row * 64 + lane * 2 + 1] = lo;
}

// =====================================================================
// K2 (mma): 4 batched linears -> split outputs. 512 thr, 16 warps m32n32.
// =====================================================================
__global__ __launch_bounds__(512) void k_gemm4() {
    extern __shared__ uint16_t smu[];
    uint16_t* Ah = smu;
    uint16_t* Al = Ah + TILE_U16;
    uint16_t* Bh = Al + TILE_U16;
    uint16_t* Bl = Bh + TILE_U16;
    int tid = threadIdx.x, lane = tid & 31, w = tid >> 5;
    int g = lane >> 2, t = lane & 3;
    int row0 = blockIdx.x * 128;
    int b = row0 >> 14;
    int which = blockIdx.y;
    int woff = which * 32768 + b * 8192;
    uint32_t* Oh = g_sph + (size_t)which * OFF32;
    uint32_t* Ol = g_spl + (size_t)which * OFF32;

    copy_tile(g_qh + (size_t)row0 * 64, g_ql + (size_t)row0 * 64, Ah, Al, tid, 512);
    copy_tile(g_wh + woff, g_wl + woff, Bh, Bl, tid, 512);
    __syncthreads();

    int wm = (w >> 2) * 32, wn = (w & 3) * 32;
    float acc[2][4][4] = {};
    warp_gemm3<2, 4>(Ah, Al, Bh, Bl, wm, wn, g, t, acc);

#pragma unroll
    for (int mt = 0; mt < 2; mt++)
#pragma unroll
        for (int nt = 0; nt < 4; nt++) {
            int row = row0 + wm + mt * 16 + g;
            int col = wn + nt * 8 + 2 * t;
            uint32_t hi, lo;
            split2(acc[mt][nt][0], acc[mt][nt][1], hi, lo);
            Oh[(size_t)row * 64 + col / 2] = hi;
            Ol[(size_t)row * 64 + col / 2] = lo;
            split2(acc[mt][nt][2], acc[mt][nt][3], hi, lo);
            Oh[(size_t)(row + 8) * 64 + col / 2] = hi;
            Ol[(size_t)(row + 8) * 64 + col / 2] = lo;
        }
}

// =====================================================================
// attention score core: per-head mma + max-free softmax.
// warp = (wp m-tile 0..7, half q-half 0..1). probs[8][4] = (1/16)*softmax.
// sumbuf: [8][128][2]. Cross-half combine via 2-warp named barrier (1+wp).
// =====================================================================
__device__ __forceinline__ void attn_probs(const uint16_t* Uh, const uint16_t* Ul,
                                           const uint16_t* Vh, const uint16_t* Vl,
                                           float* sumbuf, int wp, int half,
                                           int g, int t, float (&probs)[8][4]) {
#pragma unroll
    for (int nt = 0; nt < 8; nt++)
#pragma unroll
        for (int c = 0; c < 4; c++) probs[nt][c] = 0.0f;

    int row0 = wp * 16 + g;
    for (int h = 0; h < 8; h++) {
        int k = h * 16 + 2 * t;
        uint32_t ah[4], al[4];
        lda(Uh, row0, k, ah);
        lda(Ul, row0, k, al);
        float sacc[8][4];
#pragma unroll
        for (int nt = 0; nt < 8; nt++) {
#pragma unroll
            for (int c = 0; c < 4; c++) sacc[nt][c] = 0.0f;
            int n = half * 64 + nt * 8 + g;
            uint32_t bh[2], bl[2];
            ldb(Vh, n, k, bh);
            ldb(Vl, n, k, bl);
            mma_bf16(sacc[nt], ah, bh);
            mma_bf16(sacc[nt], ah, bl);
            mma_bf16(sacc[nt], al, bh);
        }
        float s0 = 0.0f, s1 = 0.0f;
#pragma unroll
        for (int nt = 0; nt < 8; nt++) {
            sacc[nt][0] = __expf(0.25f * sacc[nt][0]);
            sacc[nt][1] = __expf(0.25f * sacc[nt][1]);
            sacc[nt][2] = __expf(0.25f * sacc[nt][2]);
            sacc[nt][3] = __expf(0.25f * sacc[nt][3]);
            s0 += sacc[nt][0] + sacc[nt][1];
            s1 += sacc[nt][2] + sacc[nt][3];
        }
        s0 += __shfl_xor_sync(0xffffffffu, s0, 1);
        s0 += __shfl_xor_sync(0xffffffffu, s0, 2);
        s1 += __shfl_xor_sync(0xffffffffu, s1, 1);
        s1 += __shfl_xor_sync(0xffffffffu, s1, 2);
        if (t == 0) {
            sumbuf[(h * 128 + row0) * 2 + half] = s0;
            sumbuf[(h * 128 + row0 + 8) * 2 + half] = s1;
        }
        BAR2W(1 + wp);   // only the two warps sharing this row-group
        float inv0 = 1.0f / (16.0f * (sumbuf[(h * 128 + row0) * 2] +
                                      sumbuf[(h * 128 + row0) * 2 + 1]));
        float inv1 = 1.0f / (16.0f * (sumbuf[(h * 128 + row0 + 8) * 2] +
                                      sumbuf[(h * 128 + row0 + 8) * 2 + 1]));
#pragma unroll
        for (int nt = 0; nt < 8; nt++) {
            probs[nt][0] = fmaf(sacc[nt][0], inv0, probs[nt][0]);
            probs[nt][1] = fmaf(sacc[nt][1], inv0, probs[nt][1]);
            probs[nt][2] = fmaf(sacc[nt][2], inv1, probs[nt][2]);
            probs[nt][3] = fmaf(sacc[nt][3], inv1, probs[nt][3]);
        }
    }
}

// =====================================================================
// K3: time attention. block=(b,c), 512 thr. scores mma + PV mma (atomics).
// =====================================================================
__global__ __launch_bounds__(512) void k_time_attn() {
    extern __shared__ uint16_t smu[];
    uint16_t* Uh = smu;
    uint16_t* Ul = Uh + TILE_U16;
    uint16_t* Vh = Ul + TILE_U16;
    uint16_t* Vl = Vh + TILE_U16;
    float* sumbuf = (float*)(Vl + TILE_U16);     // 8KB
    // phase-2 aliases
    uint16_t* Qth = Uh;
    uint16_t* Qtl = Ul;

    int tid = threadIdx.x, lane = tid & 31, w = tid >> 5;
    int g = lane >> 2, t = lane & 3;
    int wp = w & 7, half = w >> 3;
    int bid = blockIdx.x;
    size_t base = (size_t)bid * 16384;

    copy_tile(g_sph + (size_t)bid * 8192, g_spl + (size_t)bid * 8192, Uh, Ul, tid, 512);
    copy_tile(g_sph + OFF32 + (size_t)bid * 8192, g_spl + OFF32 + (size_t)bid * 8192,
              Vh, Vl, tid, 512);
    __syncthreads();

    float probs[8][4];
    attn_probs(Uh, Ul, Vh, Vl, sumbuf, wp, half, g, t, probs);
    __syncthreads();

    // qzn^T split directly from global (coalesced along d) into U area
    for (int i = tid; i < 8192; i += 512) {
        int d = i & 127, j = i >> 7;
        float x0 = g_qzn[base + (size_t)(2 * j) * 128 + d];
        float x1 = g_qzn[base + (size_t)(2 * j + 1) * 128 + d];
        uint32_t hi, lo; split2(x0, x1, hi, lo);
        *(uint32_t*)(Qth + d * SA + 2 * j) = hi;
        *(uint32_t*)(Qtl + d * SA + 2 * j) = lo;
    }
    __syncthreads();

    // PV: m[p][d] = sum_q P[p][q] Qn[q][d]; warp's k-range = its q-half.
    int prow = wp * 16 + g;
    for (int pass = 0; pass < 2; pass++) {
        float accp[8][4] = {};
#pragma unroll
        for (int kt = 0; kt < 4; kt++) {
            int k = half * 64 + kt * 16 + 2 * t;
            uint32_t ah[4], al[4];
            split2(probs[2 * kt][0], probs[2 * kt][1], ah[0], al[0]);
            split2(probs[2 * kt][2], probs[2 * kt][3], ah[1], al[1]);
            split2(probs[2 * kt + 1][0], probs[2 * kt + 1][1], ah[2], al[2]);
            split2(probs[2 * kt + 1][2], probs[2 * kt + 1][3], ah[3], al[3]);
#pragma unroll
            for (int nt = 0; nt < 8; nt++) {
                int n = pass * 64 + nt * 8 + g;
                uint32_t bh[2], bl[2];
                ldb(Qth, n, k, bh);
                ldb(Qtl, n, k, bl);
                mma_bf16(accp[nt], ah, bh);
                mma_bf16(accp[nt], ah, bl);
                mma_bf16(accp[nt], al, bh);
            }
        }
#pragma unroll
        for (int nt = 0; nt < 8; nt++) {
            int col = pass * 64 + nt * 8 + 2 * t;
            atomicAdd(&g_xacc[base + (size_t)prow * 128 + col], accp[nt][0]);
            atomicAdd(&g_xacc[base + (size_t)prow * 128 + col + 1], accp[nt][1]);
            atomicAdd(&g_xacc[base + (size_t)(prow + 8) * 128 + col], accp[nt][2]);
            atomicAdd(&g_xacc[base + (size_t)(prow + 8) * 128 + col + 1], accp[nt][3]);
        }
    }
}

// =====================================================================
// K4: channel attention. block=(b,p), 512 thr. scores mma + elementwise.
// =====================================================================
__global__ __launch_bounds__(512) void k_chan_attn() {
    extern __shared__ uint16_t smu[];
    uint16_t* Uh = smu;
    uint16_t* Ul = Uh + TILE_U16;
    uint16_t* Vh = Ul + TILE_U16;
    uint16_t* Vl = Vh + TILE_U16;
    float* sumbuf = (float*)(Vl + TILE_U16);

    int tid = threadIdx.x, lane = tid & 31, w = tid >> 5;
    int g = lane >> 2, t = lane & 3;
    int wp = w & 7, half = w >> 3;
    int bp = blockIdx.x;
    int b = bp >> 7, p = bp & 127;
    size_t rowbase = (size_t)b * 16384 + p;
    size_t bbase = (size_t)b * 2097152 + (size_t)p * 128;

    copy_tile_strided(g_sph + 2 * (size_t)OFF32, g_spl + 2 * (size_t)OFF32,
                      rowbase, 128, Uh, Ul, tid, 512);
    copy_tile_strided(g_sph + 3 * (size_t)OFF32, g_spl + 3 * (size_t)OFF32,
                      rowbase, 128, Vh, Vl, tid, 512);
    __syncthreads();

    float probs[8][4];
    attn_probs(Uh, Ul, Vh, Vl, sumbuf, wp, half, g, t, probs);

    int c0 = wp * 16 + g;
#pragma unroll
    for (int nt = 0; nt < 8; nt++) {
        int col = half * 64 + nt * 8 + 2 * t;
        size_t g0 = bbase + (size_t)c0 * 16384 + col;
        size_t g1 = bbase + (size_t)(c0 + 8) * 16384 + col;
        float2 q0 = *(const float2*)(g_qzn + g0);
        float2 q1 = *(const float2*)(g_qzn + g1);
        float2 x0 = *(const float2*)(g_xacc + g0);
        float2 x1 = *(const float2*)(g_xacc + g1);
        x0.x += probs[nt][0] * q0.x;
        x0.y += probs[nt][1] * q0.y;
        x1.x += probs[nt][2] * q1.x;
        x1.y += probs[nt][3] * q1.y;
        *(float2*)(g_xacc + g0) = x0;
        *(float2*)(g_xacc + g1) = x1;
    }
}

// =====================================================================
// K5 (mma): topic. 128 rows/block, 512 thr (16 warps, m32 x n32), 512 blk.
// =====================================================================
__global__ __launch_bounds__(512) void k_topic() {
    extern __shared__ uint16_t smu[];
    uint16_t* Qh = smu;
    uint16_t* Ql = Qh + TILE_U16;
    uint16_t* Bh = Ql + TILE_U16;
    uint16_t* Bl = Bh + TILE_U16;
    uint16_t* Sh = Bl + TILE_U16;
    uint16_t* Sl = Sh + TILE_U16;
    float* rs = (float*)(Sl + TILE_U16);
    int tid = threadIdx.x, lane = tid & 31, w = tid >> 5;
    int g = lane >> 2, t = lane & 3;
    int wm = (w >> 2) * 32, wn = (w & 3) * 32;
    int row0 = blockIdx.x * 128;
    int b = row0 >> 14;

    copy_tile(g_qh + (size_t)row0 * 64, g_ql + (size_t)row0 * 64, Qh, Ql, tid, 512);
    if (tid < 128) rs[tid] = 0.0f;

    float macc[2][4][4] = {};

    for (int gc = 0; gc < 4; gc++) {
        int noff = b * 32768 + gc * 8192;
        __syncthreads();
        copy_tile(g_tnh + noff, g_tnl + noff, Bh, Bl, tid, 512);
        __syncthreads();

        float sacc[2][4][4] = {};
        warp_gemm3<2, 4>(Qh, Ql, Bh, Bl, wm, wn, g, t, sacc);
        __syncthreads();

#pragma unroll
        for (int mt = 0; mt < 2; mt++) {
            int row = wm + mt * 16 + g;
            float p0 = 0.f, p1 = 0.f;
#pragma unroll
            for (int nt = 0; nt < 4; nt++) {
                float r0 = fmaxf(sacc[mt][nt][0], 0.f);
                float r1 = fmaxf(sacc[mt][nt][1], 0.f);
                float r2 = fmaxf(sacc[mt][nt][2], 0.f);
                float r3 = fmaxf(sacc[mt][nt][3], 0.f);
                p0 += r0 + r1;
                p1 += r2 + r3;
                int col = wn + nt * 8 + 2 * t;
                uint32_t hi, lo;
                split2(r0, r1, hi, lo);
                *(uint32_t*)(Sh + row * SA + col) = hi;
                *(uint32_t*)(Sl + row * SA + col) = lo;
                split2(r2, r3, hi, lo);
                *(uint32_t*)(Sh + (row + 8) * SA + col) = hi;
                *(uint32_t*)(Sl + (row + 8) * SA + col) = lo;
            }
            p0 += __shfl_xor_sync(0xffffffffu, p0, 1);
            p0 += __shfl_xor_sync(0xffffffffu, p0, 2);
            p1 += __shfl_xor_sync(0xffffffffu, p1, 1);
            p1 += __shfl_xor_sync(0xffffffffu, p1, 2);
            if (t == 0) {
                atomicAdd(rs + row, p0);
                atomicAdd(rs + row + 8, p1);
            }
        }
        copy_tile(g_tth + noff, g_ttl + noff, Bh, Bl, tid, 512);
        __syncthreads();

        warp_gemm3<2, 4>(Sh, Sl, Bh, Bl, wm, wn, g, t, macc);
    }
    __syncthreads();

#pragma unroll
    for (int mt = 0; mt < 2; mt++) {
        int row = wm + mt * 16 + g;
        float idn0 = 0.5f / fmaxf(rs[row], 1e-6f);
        float idn1 = 0.5f / fmaxf(rs[row + 8], 1e-6f);
#pragma unroll
        for (int nt = 0; nt < 4; nt++) {
            int col = wn + nt * 8 + 2 * t;
            size_t g0 = (size_t)(row0 + row) * 128 + col;
            size_t g1 = (size_t)(row0 + row + 8) * 128 + col;
            float2 x0 = *(float2*)(g_xacc + g0);
            float2 x1 = *(float2*)(g_xacc + g1);
            x0.x += macc[mt][nt][0] * idn0;
            x0.y += macc[mt][nt][1] * idn0;
            x1.x += macc[mt][nt][2] * idn1;
            x1.y += macc[mt][nt][3] * idn1;
            *(float2*)(g_xacc + g0) = x0;
            *(float2*)(g_xacc + g1) = x1;
        }
    }
}

// =====================================================================
// K6 (mma): mlp. 128 rows/block, 512 thr, 16 warps m32n32.
// =====================================================================
__global__ __launch_bounds__(512) void k_mlp(
    const float* __restrict__ gamma, const float* __restrict__ beta,
    const float* __restrict__ b1, const float* __restrict__ b2,
    float* __restrict__ out) {
    extern __shared__ uint16_t smu[];
    uint16_t* Ah = smu;
    uint16_t* Al = Ah + TILE_U16;
    uint16_t* Bh = Al + TILE_U16;
    uint16_t* Bl = Bh + TILE_U16;
    int tid = threadIdx.x, lane = tid & 31, w = tid >> 5;
    int g = lane >> 2, t = lane & 3;
    int row0 = blockIdx.x * 128;
    int wm = (w >> 2) * 32, wn = (w & 3) * 32;

    float4 g4 = *(const float4*)(gamma + lane * 4);
    float4 b4 = *(const float4*)(beta + lane * 4);
#pragma unroll
    for (int it = 0; it < 8; it++) {
        int r = w * 8 + it;
        size_t gb = (size_t)(row0 + r) * 128 + lane * 4;
        float4 v = *(const float4*)(g_xacc + gb);
        float s = v.x + v.y + v.z + v.w;
        float ss = v.x * v.x + v.y * v.y + v.z * v.z + v.w * v.w;
#pragma unroll
        for (int o = 16; o > 0; o >>= 1) {
            s += __shfl_xor_sync(0xffffffffu, s, o);
            ss += __shfl_xor_sync(0xffffffffu, ss, o);
        }
        float m = s * (1.0f / 128.0f);
        float var = ss * (1.0f / 128.0f) - m * m;
        float inv = rsqrtf(var + 1e-5f);
        float q0 = (v.x - m) * inv * g4.x + b4.x;
        float q1 = (v.y - m) * inv * g4.y + b4.y;
        float q2 = (v.z - m) * inv * g4.z + b4.z;
        float q3 = (v.w - m) * inv * g4.w + b4.w;
        uint32_t hi, lo;
        split2(q0, q1, hi, lo);
        *(uint32_t*)(Ah + r * SA + lane * 4) = hi;
        *(uint32_t*)(Al + r * SA + lane * 4) = lo;
        split2(q2, q3, hi, lo);
        *(uint32_t*)(Ah + r * SA + lane * 4 + 2) = hi;
        *(uint32_t*)(Al + r * SA + lane * 4 + 2) = lo;
    }
    copy_tile(g_w1h, g_w1l, Bh, Bl, tid, 512);
    __syncthreads();

    float acc[2][4][4] = {};
    warp_gemm3<2, 4>(Ah, Al, Bh, Bl, wm, wn, g, t, acc);
    __syncthreads();

#pragma unroll
    for (int mt = 0; mt < 2; mt++)
#pragma unroll
        for (int nt = 0; nt < 4; nt++) {
            int row = wm + mt * 16 + g;
            int col = wn + nt * 8 + 2 * t;
            float bb0 = b1[col], bb1 = b1[col + 1];
            float x0 = acc[mt][nt][0] + bb0, x1 = acc[mt][nt][1] + bb1;
            float x2 = acc[mt][nt][2] + bb0, x3 = acc[mt][nt][3] + bb1;
            float gl0 = 0.5f * x0 * (1.0f + erff(x0 * 0.70710678118654752f));
            float gl1 = 0.5f * x1 * (1.0f + erff(x1 * 0.70710678118654752f));
            float gl2 = 0.5f * x2 * (1.0f + erff(x2 * 0.70710678118654752f));
            float gl3 = 0.5f * x3 * (1.0f + erff(x3 * 0.70710678118654752f));
            uint32_t hi, lo;
            split2(gl0, gl1, hi, lo);
            *(uint32_t*)(Ah + row * SA + col) = hi;
            *(uint32_t*)(Al + row * SA + col) = lo;
            split2(gl2, gl3, hi, lo);
            *(uint32_t*)(Ah + (row + 8) * SA + col) = hi;
            *(uint32_t*)(Al + (row + 8) * SA + col) = lo;
        }
    copy_tile(g_w2h, g_w2l, Bh, Bl, tid, 512);
    __syncthreads();

    float acc2[2][4][4] = {};
    warp_gemm3<2, 4>(Ah, Al, Bh, Bl, wm, wn, g, t, acc2);

#pragma unroll
    for (int mt = 0; mt < 2; mt++)
#pragma unroll
        for (int nt = 0; nt < 4; nt++) {
            int row = row0 + wm + mt * 16 + g;
            int col = wn + nt * 8 + 2 * t;
            float bb0 = b2[col], bb1 = b2[col + 1];
            size_t g0 = (size_t)row * 128 + col;
            size_t g1 = (size_t)(row + 8) * 128 + col;
            float2 x0 = *(const float2*)(g_xacc + g0);
            float2 x1 = *(const float2*)(g_xacc + g1);
            float2 o0 = {x0.x + acc2[mt][nt][0] + bb0, x0.y + acc2[mt][nt][1] + bb1};
            float2 o1 = {x1.x + acc2[mt][nt][2] + bb0, x1.y + acc2[mt][nt][3] + bb1};
            *(float2*)(out + g0) = o0;
            *(float2*)(out + g1) = o1;
        }
}

// =====================================================================
// launch
// =====================================================================
extern "C" void kernel_launch(void* const* d_in, const int* in_sizes, int n_in,
                              void* d_out, int out_size) {
    const float* qz    = (const float*)d_in[0];
    const float* unary = (const float*)d_in[1];
    const float* tuw   = (const float*)d_in[2];
    const float* tvw   = (const float*)d_in[3];
    const float* cuw   = (const float*)d_in[4];
    const float* cvw   = (const float*)d_in[5];
    const float* topic = (const float*)d_in[6];
    const float* gamma = (const float*)d_in[7];
    const float* beta  = (const float*)d_in[8];
    const float* w1    = (const float*)d_in[9];
    const float* b1    = (const float*)d_in[10];
    const float* w2    = (const float*)d_in[11];
    const float* b2    = (const float*)d_in[12];
    float* out = (float*)d_out;

    const int SMG = 4 * TILE_U16 * 2;                   // 139264
    const int SMA = 4 * TILE_U16 * 2 + 8192;            // 147456
    const int SMT = 6 * TILE_U16 * 2 + 512;             // 209408

    cudaFuncSetAttribute(k_gemm4, cudaFuncAttributeMaxDynamicSharedMemorySize, SMG);
    cudaFuncSetAttribute(k_time_attn, cudaFuncAttributeMaxDynamicSharedMemorySize, SMA);
    cudaFuncSetAttribute(k_chan_attn, cudaFuncAttributeMaxDynamicSharedMemorySize, SMA);
    cudaFuncSetAttribute(k_topic, cudaFuncAttributeMaxDynamicSharedMemorySize, SMT);
    cudaFuncSetAttribute(k_mlp, cudaFuncAttributeMaxDynamicSharedMemorySize, SMG);

    k_prep<<<256, 256>>>(tuw, tvw, cuw, cvw, topic, w1, w2);
    k_ln_init<<<NROW / 8, 256>>>(qz, unary, gamma, beta);
    k_gemm4<<<dim3(NROW / 128, 4), 512, SMG>>>();
    k_time_attn<<<NB * NC, 512, SMA>>>();
    k_chan_attn<<<NB * NP, 512, SMA>>>();
    k_topic<<<NROW / 128, 512, SMT>>>();
    k_mlp<<<NROW / 128, 512, SMG>>>(gamma, beta, b1, b2, out);
}

// round 13
// speedup vs baseline: 1.0569x; 1.0396x over previous
#include <cuda_runtime.h>
#include <cuda_bf16.h>
#include <stdint.h>
#include <math.h>

#define NB 4
#define NC 128
#define NP 128
#define ND 128
#define NG 512
#define NROW (NB * NC * NP)            // 65536
#define NELEM ((size_t)NROW * ND)      // 8388608

typedef unsigned long long u64;

#define SA 136                         // bf16 stride for mma tiles
#define TILE_U16 (128 * SA)            // 17408 uint16 per tile
#define OFF32 (NROW * 64)              // u32 per split buffer

// -------------------- scratch --------------------
__device__ float g_qzn[NELEM];
__device__ float g_xacc[NELEM];

// packed bf16x2 (hi/lo split) buffers
__device__ uint32_t g_qh[OFF32], g_ql[OFF32];                  // qzn split
__device__ uint32_t g_sph[4 * OFF32], g_spl[4 * OFF32];        // tu/tv/cu/cv outputs split
__device__ uint32_t g_wh[4 * 4 * 8192], g_wl[4 * 4 * 8192];    // attention weights
__device__ uint32_t g_tnh[4 * 512 * 64], g_tnl[4 * 512 * 64];  // topic natural
__device__ uint32_t g_tth[4 * 4 * 8192], g_ttl[4 * 4 * 8192];  // topic transposed
__device__ uint32_t g_w1h[8192], g_w1l[8192];
__device__ uint32_t g_w2h[8192], g_w2l[8192];

// -------------------- helpers --------------------
__device__ __forceinline__ uint32_t pkbf(__nv_bfloat16 a, __nv_bfloat16 b) {
    return (uint32_t)__bfloat16_as_ushort(a) | ((uint32_t)__bfloat16_as_ushort(b) << 16);
}
__device__ __forceinline__ void split2(float x0, float x1, uint32_t &hi, uint32_t &lo) {
    __nv_bfloat16 h0 = __float2bfloat16(x0), h1 = __float2bfloat16(x1);
    hi = pkbf(h0, h1);
    lo = pkbf(__float2bfloat16(x0 - __bfloat162float(h0)),
              __float2bfloat16(x1 - __bfloat162float(h1)));
}

__device__ __forceinline__ void mma_bf16(float* c, const uint32_t* a, const uint32_t* b) {
    asm volatile(
        "mma.sync.aligned.m16n8k16.row.col.f32.bf16.bf16.f32 "
        "{%0,%1,%2,%3}, {%4,%5,%6,%7}, {%8,%9}, {%0,%1,%2,%3};"
        : "+f"(c[0]), "+f"(c[1]), "+f"(c[2]), "+f"(c[3])
        : "r"(a[0]), "r"(a[1]), "r"(a[2]), "r"(a[3]), "r"(b[0]), "r"(b[1]));
}

__device__ __forceinline__ void lda(const uint16_t* A, int r, int k, uint32_t* f) {
    const uint16_t* p = A + r * SA + k;
    f[0] = *(const uint32_t*)p;
    f[1] = *(const uint32_t*)(p + 8 * SA);
    f[2] = *(const uint32_t*)(p + 8);
    f[3] = *(const uint32_t*)(p + 8 * SA + 8);
}
__device__ __forceinline__ void ldb(const uint16_t* B, int n, int k, uint32_t* f) {
    const uint16_t* p = B + n * SA + k;
    f[0] = *(const uint32_t*)p;
    f[1] = *(const uint32_t*)(p + 8);
}

// copy packed-u32 contiguous global tile [rows][64] into smem u16 tile
template <int ROWS>
__device__ __forceinline__ void copy_tileN(const uint32_t* __restrict__ srch,
                                           const uint32_t* __restrict__ srcl,
                                           uint16_t* Ah, uint16_t* Al,
                                           int tid, int nthr) {
    const u64* sh = (const u64*)srch;
    const u64* sl = (const u64*)srcl;
    for (int i = tid; i < ROWS * 32; i += nthr) {
        int r = i >> 5, c4 = (i & 31) * 4;
        *(u64*)(Ah + r * SA + c4) = sh[i];
        *(u64*)(Al + r * SA + c4) = sl[i];
    }
}
#define copy_tile(sh, sl, Ah, Al, tid, nthr) copy_tileN<128>(sh, sl, Ah, Al, tid, nthr)

__device__ __forceinline__ void copy_tile_strided(const uint32_t* __restrict__ srch,
                                                  const uint32_t* __restrict__ srcl,
                                                  size_t row_base, int row_stride,
                                                  uint16_t* Ah, uint16_t* Al,
                                                  int tid, int nthr) {
    for (int i = tid; i < 4096; i += nthr) {
        int r = i >> 5, j = i & 31;
        size_t s = (row_base + (size_t)r * row_stride) * 32 + j;
        *(u64*)(Ah + r * SA + j * 4) = ((const u64*)srch)[s];
        *(u64*)(Al + r * SA + j * 4) = ((const u64*)srcl)[s];
    }
}

// 3-term warp GEMM
template <int MT, int NT>
__device__ __forceinline__ void warp_gemm3(
    const uint16_t* Ah, const uint16_t* Al,
    const uint16_t* Bh, const uint16_t* Bl,
    int wm, int wn, int g, int t, float (&acc)[MT][NT][4]) {
#pragma unroll
    for (int kt = 0; kt < 8; kt++) {
        int k = kt * 16 + 2 * t;
        uint32_t bh[NT][2], bl[NT][2];
#pragma unroll
        for (int nt = 0; nt < NT; nt++) {
            int n = wn + nt * 8 + g;
            ldb(Bh, n, k, bh[nt]);
            ldb(Bl, n, k, bl[nt]);
        }
#pragma unroll
        for (int mt = 0; mt < MT; mt++) {
            uint32_t ah[4], al[4];
            int r = wm + mt * 16 + g;
            lda(Ah, r, k, ah);
            lda(Al, r, k, al);
#pragma unroll
            for (int nt = 0; nt < NT; nt++) {
                mma_bf16(acc[mt][nt], ah, bh[nt]);
                mma_bf16(acc[mt][nt], ah, bl[nt]);
                mma_bf16(acc[mt][nt], al, bh[nt]);
            }
        }
    }
}

// =====================================================================
// K0: prep — split all static weights once.
// =====================================================================
__global__ __launch_bounds__(256) void k_prep(
    const float* __restrict__ tuw, const float* __restrict__ tvw,
    const float* __restrict__ cuw, const float* __restrict__ cvw,
    const float* __restrict__ topic,
    const float* __restrict__ w1, const float* __restrict__ w2) {
    int tid = blockIdx.x * 256 + threadIdx.x;
    int nth = gridDim.x * 256;
    for (int i = tid; i < 4 * 4 * 8192; i += nth) {
        int which = i >> 15;
        int rem = i & 32767;
        const float* W = (which == 0 ? tuw : which == 1 ? tvw : which == 2 ? cuw : cvw);
        float2 v = *(const float2*)(W + (size_t)rem * 2);
        uint32_t hi, lo; split2(v.x, v.y, hi, lo);
        g_wh[i] = hi; g_wl[i] = lo;
    }
    for (int i = tid; i < 4 * 512 * 64; i += nth) {
        float2 v = *(const float2*)(topic + (size_t)i * 2);
        uint32_t hi, lo; split2(v.x, v.y, hi, lo);
        g_tnh[i] = hi; g_tnl[i] = lo;
    }
    for (int i = tid; i < 4 * 4 * 8192; i += nth) {
        int b = i >> 15;
        int gc = (i >> 13) & 3;
        int d = (i >> 6) & 127;
        int g2 = i & 63;
        int grow = gc * 128 + g2 * 2;
        float x0 = topic[((size_t)b * 512 + grow) * 128 + d];
        float x1 = topic[((size_t)b * 512 + grow + 1) * 128 + d];
        uint32_t hi, lo; split2(x0, x1, hi, lo);
        g_tth[i] = hi; g_ttl[i] = lo;
    }
    for (int i = tid; i < 8192; i += nth) {
        float2 v = *(const float2*)(w1 + (size_t)i * 2);
        uint32_t hi, lo; split2(v.x, v.y, hi, lo);
        g_w1h[i] = hi; g_w1l[i] = lo;
        float2 u = *(const float2*)(w2 + (size_t)i * 2);
        split2(u.x, u.y, hi, lo);
        g_w2h[i] = hi; g_w2l[i] = lo;
    }
}

// =====================================================================
// K1: qzn = LN(qz) (fp32 + split); xacc = 0.5*(qz + unary).
// =====================================================================
__global__ __launch_bounds__(256) void k_ln_init(
    const float* __restrict__ qz, const float* __restrict__ unary,
    const float* __restrict__ gamma, const float* __restrict__ beta) {
    int row = blockIdx.x * 8 + (threadIdx.x >> 5);
    int lane = threadIdx.x & 31;
    size_t base = (size_t)row * 128 + lane * 4;
    float4 v = *(const float4*)(qz + base);
    float s = v.x + v.y + v.z + v.w;
    float ss = v.x * v.x + v.y * v.y + v.z * v.z + v.w * v.w;
#pragma unroll
    for (int o = 16; o > 0; o >>= 1) {
        s += __shfl_xor_sync(0xffffffffu, s, o);
        ss += __shfl_xor_sync(0xffffffffu, ss, o);
    }
    float m = s * (1.0f / 128.0f);
    float var = ss * (1.0f / 128.0f) - m * m;
    float inv = rsqrtf(var + 1e-5f);
    float4 u = *(const float4*)(unary + base);
    float4 g4 = *(const float4*)(gamma + lane * 4);
    float4 b4 = *(const float4*)(beta + lane * 4);
    float4 qn, xa;
    qn.x = (v.x - m) * inv * g4.x + b4.x;
    qn.y = (v.y - m) * inv * g4.y + b4.y;
    qn.z = (v.z - m) * inv * g4.z + b4.z;
    qn.w = (v.w - m) * inv * g4.w + b4.w;
    xa.x = 0.5f * (v.x + u.x);
    xa.y = 0.5f * (v.y + u.y);
    xa.z = 0.5f * (v.z + u.z);
    xa.w = 0.5f * (v.w + u.w);
    *(float4*)(g_qzn + base) = qn;
    *(float4*)(g_xacc + base) = xa;
    uint32_t hi, lo;
    split2(qn.x, qn.y, hi, lo);
    g_qh[row * 64 + lane * 2] = hi;
    g_ql[row * 64 + lane * 2] = lo;
    split2(qn.z, qn.w, hi, lo);
    g_qh[row * 64 + lane * 2 + 1] = hi;
    g_ql[row * 64 + lane * 2 + 1] = lo;
}

// =====================================================================
// K2 (mma): 4 batched linears, 256 rows/block, loop over 4 weights.
// 512 thr, 16 warps m64n32. grid = 256.
// =====================================================================
__global__ __launch_bounds__(512) void k_gemm4() {
    extern __shared__ uint16_t smu[];
    uint16_t* Ah = smu;                        // 256 rows
    uint16_t* Al = Ah + 2 * TILE_U16;
    uint16_t* Bh = Al + 2 * TILE_U16;          // 128 rows
    uint16_t* Bl = Bh + TILE_U16;
    int tid = threadIdx.x, lane = tid & 31, w = tid >> 5;
    int g = lane >> 2, t = lane & 3;
    int row0 = blockIdx.x * 256;
    int b = row0 >> 14;
    int wm = (w >> 2) * 64, wn = (w & 3) * 32;

    copy_tileN<256>(g_qh + (size_t)row0 * 64, g_ql + (size_t)row0 * 64, Ah, Al, tid, 512);

    for (int which = 0; which < 4; which++) {
        int woff = which * 32768 + b * 8192;
        uint32_t* Oh = g_sph + (size_t)which * OFF32;
        uint32_t* Ol = g_spl + (size_t)which * OFF32;
        if (which > 0) __syncthreads();        // prior gemm done reading B
        copy_tile(g_wh + woff, g_wl + woff, Bh, Bl, tid, 512);
        __syncthreads();

        float acc[4][4][4] = {};
        warp_gemm3<4, 4>(Ah, Al, Bh, Bl, wm, wn, g, t, acc);

#pragma unroll
        for (int mt = 0; mt < 4; mt++)
#pragma unroll
            for (int nt = 0; nt < 4; nt++) {
                int row = row0 + wm + mt * 16 + g;
                int col = wn + nt * 8 + 2 * t;
                uint32_t hi, lo;
                split2(acc[mt][nt][0], acc[mt][nt][1], hi, lo);
                Oh[(size_t)row * 64 + col / 2] = hi;
                Ol[(size_t)row * 64 + col / 2] = lo;
                split2(acc[mt][nt][2], acc[mt][nt][3], hi, lo);
                Oh[(size_t)(row + 8) * 64 + col / 2] = hi;
                Ol[(size_t)(row + 8) * 64 + col / 2] = lo;
            }
    }
}

// =====================================================================
// attention score core (R9): per-head mma + max-free softmax.
// warp = (wp m-tile 0..7, half q-half 0..1). probs[8][4] = (1/16)*softmax.
// sumbuf: [8][128][2] floats (8KB).
// =====================================================================
__device__ __forceinline__ void attn_probs(const uint16_t* Uh, const uint16_t* Ul,
                                           const uint16_t* Vh, const uint16_t* Vl,
                                           float* sumbuf, int wp, int half,
                                           int g, int t, float (&probs)[8][4]) {
#pragma unroll
    for (int nt = 0; nt < 8; nt++)
#pragma unroll
        for (int c = 0; c < 4; c++) probs[nt][c] = 0.0f;

    int row0 = wp * 16 + g;
    for (int h = 0; h < 8; h++) {
        int k = h * 16 + 2 * t;
        uint32_t ah[4], al[4];
        lda(Uh, row0, k, ah);
        lda(Ul, row0, k, al);
        float sacc[8][4];
#pragma unroll
        for (int nt = 0; nt < 8; nt++) {
#pragma unroll
            for (int c = 0; c < 4; c++) sacc[nt][c] = 0.0f;
            int n = half * 64 + nt * 8 + g;
            uint32_t bh[2], bl[2];
            ldb(Vh, n, k, bh);
            ldb(Vl, n, k, bl);
            mma_bf16(sacc[nt], ah, bh);
            mma_bf16(sacc[nt], ah, bl);
            mma_bf16(sacc[nt], al, bh);
        }
        float s0 = 0.0f, s1 = 0.0f;
#pragma unroll
        for (int nt = 0; nt < 8; nt++) {
            sacc[nt][0] = __expf(0.25f * sacc[nt][0]);
            sacc[nt][1] = __expf(0.25f * sacc[nt][1]);
            sacc[nt][2] = __expf(0.25f * sacc[nt][2]);
            sacc[nt][3] = __expf(0.25f * sacc[nt][3]);
            s0 += sacc[nt][0] + sacc[nt][1];
            s1 += sacc[nt][2] + sacc[nt][3];
        }
        s0 += __shfl_xor_sync(0xffffffffu, s0, 1);
        s0 += __shfl_xor_sync(0xffffffffu, s0, 2);
        s1 += __shfl_xor_sync(0xffffffffu, s1, 1);
        s1 += __shfl_xor_sync(0xffffffffu, s1, 2);
        if (t == 0) {
            sumbuf[(h * 128 + row0) * 2 + half] = s0;
            sumbuf[(h * 128 + row0 + 8) * 2 + half] = s1;
        }
        __syncthreads();
        float inv0 = 1.0f / (16.0f * (sumbuf[(h * 128 + row0) * 2] +
                                      sumbuf[(h * 128 + row0) * 2 + 1]));
        float inv1 = 1.0f / (16.0f * (sumbuf[(h * 128 + row0 + 8) * 2] +
                                      sumbuf[(h * 128 + row0 + 8) * 2 + 1]));
#pragma unroll
        for (int nt = 0; nt < 8; nt++) {
            probs[nt][0] = fmaf(sacc[nt][0], inv0, probs[nt][0]);
            probs[nt][1] = fmaf(sacc[nt][1], inv0, probs[nt][1]);
            probs[nt][2] = fmaf(sacc[nt][2], inv1, probs[nt][2]);
            probs[nt][3] = fmaf(sacc[nt][3], inv1, probs[nt][3]);
        }
    }
}

// =====================================================================
// K3: time attention (R9 exact). block=(b,c), 512 thr.
// =====================================================================
__global__ __launch_bounds__(512) void k_time_attn() {
    extern __shared__ uint16_t smu[];
    uint16_t* Uh = smu;
    uint16_t* Ul = Uh + TILE_U16;
    uint16_t* Vh = Ul + TILE_U16;
    uint16_t* Vl = Vh + TILE_U16;
    float* sumbuf = (float*)(Vl + TILE_U16);     // 8KB
    // phase-2 aliases
    uint16_t* Qth = Uh;
    uint16_t* Qtl = Ul;
    float* qs = (float*)Vh;                       // [128][129] fp32 stage

    int tid = threadIdx.x, lane = tid & 31, w = tid >> 5;
    int g = lane >> 2, t = lane & 3;
    int wp = w & 7, half = w >> 3;
    int bid = blockIdx.x;
    size_t base = (size_t)bid * 16384;

    copy_tile(g_sph + (size_t)bid * 8192, g_spl + (size_t)bid * 8192, Uh, Ul, tid, 512);
    copy_tile(g_sph + OFF32 + (size_t)bid * 8192, g_spl + OFF32 + (size_t)bid * 8192,
              Vh, Vl, tid, 512);
    __syncthreads();

    float probs[8][4];
    attn_probs(Uh, Ul, Vh, Vl, sumbuf, wp, half, g, t, probs);
    __syncthreads();

    // stage qzn fp32 into V area, then split-transpose into U area
    for (int i = tid; i < 16384; i += 512) {
        int q = i >> 7, d = i & 127;
        qs[q * 129 + d] = g_qzn[base + i];
    }
    __syncthreads();
    for (int i = tid; i < 8192; i += 512) {
        int d = i & 127, j = i >> 7;
        float x0 = qs[(2 * j) * 129 + d];
        float x1 = qs[(2 * j + 1) * 129 + d];
        uint32_t hi, lo; split2(x0, x1, hi, lo);
        *(uint32_t*)(Qth + d * SA + 2 * j) = hi;
        *(uint32_t*)(Qtl + d * SA + 2 * j) = lo;
    }
    __syncthreads();

    // PV: m[p][d] = sum_q P[p][q] Qn[q][d]; two d-passes of 64
    int prow = wp * 16 + g;
    for (int pass = 0; pass < 2; pass++) {
        float accp[8][4] = {};
#pragma unroll
        for (int kt = 0; kt < 4; kt++) {
            int k = half * 64 + kt * 16 + 2 * t;
            uint32_t ah[4], al[4];
            split2(probs[2 * kt][0], probs[2 * kt][1], ah[0], al[0]);
            split2(probs[2 * kt][2], probs[2 * kt][3], ah[1], al[1]);
            split2(probs[2 * kt + 1][0], probs[2 * kt + 1][1], ah[2], al[2]);
            split2(probs[2 * kt + 1][2], probs[2 * kt + 1][3], ah[3], al[3]);
#pragma unroll
            for (int nt = 0; nt < 8; nt++) {
                int n = pass * 64 + nt * 8 + g;
                uint32_t bh[2], bl[2];
                ldb(Qth, n, k, bh);
                ldb(Qtl, n, k, bl);
                mma_bf16(accp[nt], ah, bh);
                mma_bf16(accp[nt], ah, bl);
                mma_bf16(accp[nt], al, bh);
            }
        }
#pragma unroll
        for (int nt = 0; nt < 8; nt++) {
            int col = pass * 64 + nt * 8 + 2 * t;
            atomicAdd(&g_xacc[base + (size_t)prow * 128 + col], accp[nt][0]);
            atomicAdd(&g_xacc[base + (size_t)prow * 128 + col + 1], accp[nt][1]);
            atomicAdd(&g_xacc[base + (size_t)(prow + 8) * 128 + col], accp[nt][2]);
            atomicAdd(&g_xacc[base + (size_t)(prow + 8) * 128 + col + 1], accp[nt][3]);
        }
    }
}

// =====================================================================
// K4: channel attention (R9 exact). block=(b,p), 512 thr.
// =====================================================================
__global__ __launch_bounds__(512) void k_chan_attn() {
    extern __shared__ uint16_t smu[];
    uint16_t* Uh = smu;
    uint16_t* Ul = Uh + TILE_U16;
    uint16_t* Vh = Ul + TILE_U16;
    uint16_t* Vl = Vh + TILE_U16;
    float* sumbuf = (float*)(Vl + TILE_U16);

    int tid = threadIdx.x, lane = tid & 31, w = tid >> 5;
    int g = lane >> 2, t = lane & 3;
    int wp = w & 7, half = w >> 3;
    int bp = blockIdx.x;
    int b = bp >> 7, p = bp & 127;
    size_t rowbase = (size_t)b * 16384 + p;
    size_t bbase = (size_t)b * 2097152 + (size_t)p * 128;

    copy_tile_strided(g_sph + 2 * (size_t)OFF32, g_spl + 2 * (size_t)OFF32,
                      rowbase, 128, Uh, Ul, tid, 512);
    copy_tile_strided(g_sph + 3 * (size_t)OFF32, g_spl + 3 * (size_t)OFF32,
                      rowbase, 128, Vh, Vl, tid, 512);
    __syncthreads();

    float probs[8][4];
    attn_probs(Uh, Ul, Vh, Vl, sumbuf, wp, half, g, t, probs);

    int c0 = wp * 16 + g;
#pragma unroll
    for (int nt = 0; nt < 8; nt++) {
        int col = half * 64 + nt * 8 + 2 * t;
        size_t g0 = bbase + (size_t)c0 * 16384 + col;
        size_t g1 = bbase + (size_t)(c0 + 8) * 16384 + col;
        float2 q0 = *(const float2*)(g_qzn + g0);
        float2 q1 = *(const float2*)(g_qzn + g1);
        float2 x0 = *(const float2*)(g_xacc + g0);
        float2 x1 = *(const float2*)(g_xacc + g1);
        x0.x += probs[nt][0] * q0.x;
        x0.y += probs[nt][1] * q0.y;
        x1.x += probs[nt][2] * q1.x;
        x1.y += probs[nt][3] * q1.y;
        *(float2*)(g_xacc + g0) = x0;
        *(float2*)(g_xacc + g1) = x1;
    }
}

// =====================================================================
// K5 (mma): topic (R9 exact). 128 rows/block, 512 thr, 512 blocks.
// =====================================================================
__global__ __launch_bounds__(512) void k_topic() {
    extern __shared__ uint16_t smu[];
    uint16_t* Qh = smu;
    uint16_t* Ql = Qh + TILE_U16;
    uint16_t* Bh = Ql + TILE_U16;
    uint16_t* Bl = Bh + TILE_U16;
    uint16_t* Sh = Bl + TILE_U16;
    uint16_t* Sl = Sh + TILE_U16;
    float* rs = (float*)(Sl + TILE_U16);
    int tid = threadIdx.x, lane = tid & 31, w = tid >> 5;
    int g = lane >> 2, t = lane & 3;
    int wm = (w >> 2) * 32, wn = (w & 3) * 32;
    int row0 = blockIdx.x * 128;
    int b = row0 >> 14;

    copy_tile(g_qh + (size_t)row0 * 64, g_ql + (size_t)row0 * 64, Qh, Ql, tid, 512);
    if (tid < 128) rs[tid] = 0.0f;

    float macc[2][4][4] = {};

    for (int gc = 0; gc < 4; gc++) {
        int noff = b * 32768 + gc * 8192;
        __syncthreads();
        copy_tile(g_tnh + noff, g_tnl + noff, Bh, Bl, tid, 512);
        __syncthreads();

        float sacc[2][4][4] = {};
        warp_gemm3<2, 4>(Qh, Ql, Bh, Bl, wm, wn, g, t, sacc);
        __syncthreads();

#pragma unroll
        for (int mt = 0; mt < 2; mt++) {
            int row = wm + mt * 16 + g;
            float p0 = 0.f, p1 = 0.f;
#pragma unroll
            for (int nt = 0; nt < 4; nt++) {
                float r0 = fmaxf(sacc[mt][nt][0], 0.f);
                float r1 = fmaxf(sacc[mt][nt][1], 0.f);
                float r2 = fmaxf(sacc[mt][nt][2], 0.f);
                float r3 = fmaxf(sacc[mt][nt][3], 0.f);
                p0 += r0 + r1;
                p1 += r2 + r3;
                int col = wn + nt * 8 + 2 * t;
                uint32_t hi, lo;
                split2(r0, r1, hi, lo);
                *(uint32_t*)(Sh + row * SA + col) = hi;
                *(uint32_t*)(Sl + row * SA + col) = lo;
                split2(r2, r3, hi, lo);
                *(uint32_t*)(Sh + (row + 8) * SA + col) = hi;
                *(uint32_t*)(Sl + (row + 8) * SA + col) = lo;
            }
            p0 += __shfl_xor_sync(0xffffffffu, p0, 1);
            p0 += __shfl_xor_sync(0xffffffffu, p0, 2);
            p1 += __shfl_xor_sync(0xffffffffu, p1, 1);
            p1 += __shfl_xor_sync(0xffffffffu, p1, 2);
            if (t == 0) {
                atomicAdd(rs + row, p0);
                atomicAdd(rs + row + 8, p1);
            }
        }
        copy_tile(g_tth + noff, g_ttl + noff, Bh, Bl, tid, 512);
        __syncthreads();

        warp_gemm3<2, 4>(Sh, Sl, Bh, Bl, wm, wn, g, t, macc);
    }
    __syncthreads();

#pragma unroll
    for (int mt = 0; mt < 2; mt++) {
        int row = wm + mt * 16 + g;
        float idn0 = 0.5f / fmaxf(rs[row], 1e-6f);
        float idn1 = 0.5f / fmaxf(rs[row + 8], 1e-6f);
#pragma unroll
        for (int nt = 0; nt < 4; nt++) {
            int col = wn + nt * 8 + 2 * t;
            size_t g0 = (size_t)(row0 + row) * 128 + col;
            size_t g1 = (size_t)(row0 + row + 8) * 128 + col;
            float2 x0 = *(float2*)(g_xacc + g0);
            float2 x1 = *(float2*)(g_xacc + g1);
            x0.x += macc[mt][nt][0] * idn0;
            x0.y += macc[mt][nt][1] * idn0;
            x1.x += macc[mt][nt][2] * idn1;
            x1.y += macc[mt][nt][3] * idn1;
            *(float2*)(g_xacc + g0) = x0;
            *(float2*)(g_xacc + g1) = x1;
        }
    }
}

// =====================================================================
// K6 (mma): mlp. 256 rows/block, 512 thr, 16 warps m64n32. grid 256.
// =====================================================================
__global__ __launch_bounds__(512) void k_mlp(
    const float* __restrict__ gamma, const float* __restrict__ beta,
    const float* __restrict__ b1, const float* __restrict__ b2,
    float* __restrict__ out) {
    extern __shared__ uint16_t smu[];
    uint16_t* Ah = smu;                     // 256 rows
    uint16_t* Al = Ah + 2 * TILE_U16;
    uint16_t* Bh = Al + 2 * TILE_U16;       // 128 rows (W1 then W2)
    uint16_t* Bl = Bh + TILE_U16;
    int tid = threadIdx.x, lane = tid & 31, w = tid >> 5;
    int g = lane >> 2, t = lane & 3;
    int row0 = blockIdx.x * 256;
    int wm = (w >> 2) * 64, wn = (w & 3) * 32;

    float4 g4 = *(const float4*)(gamma + lane * 4);
    float4 b4 = *(const float4*)(beta + lane * 4);
#pragma unroll
    for (int it = 0; it < 16; it++) {
        int r = w * 16 + it;
        size_t gb = (size_t)(row0 + r) * 128 + lane * 4;
        float4 v = *(const float4*)(g_xacc + gb);
        float s = v.x + v.y + v.z + v.w;
        float ss = v.x * v.x + v.y * v.y + v.z * v.z + v.w * v.w;
#pragma unroll
        for (int o = 16; o > 0; o >>= 1) {
            s += __shfl_xor_sync(0xffffffffu, s, o);
            ss += __shfl_xor_sync(0xffffffffu, ss, o);
        }
        float m = s * (1.0f / 128.0f);
        float var = ss * (1.0f / 128.0f) - m * m;
        float inv = rsqrtf(var + 1e-5f);
        float q0 = (v.x - m) * inv * g4.x + b4.x;
        float q1 = (v.y - m) * inv * g4.y + b4.y;
        float q2 = (v.z - m) * inv * g4.z + b4.z;
        float q3 = (v.w - m) * inv * g4.w + b4.w;
        uint32_t hi, lo;
        split2(q0, q1, hi, lo);
        *(uint32_t*)(Ah + r * SA + lane * 4) = hi;
        *(uint32_t*)(Al + r * SA + lane * 4) = lo;
        split2(q2, q3, hi, lo);
        *(uint32_t*)(Ah + r * SA + lane * 4 + 2) = hi;
        *(uint32_t*)(Al + r * SA + lane * 4 + 2) = lo;
    }
    copy_tile(g_w1h, g_w1l, Bh, Bl, tid, 512);
    __syncthreads();

    float acc[4][4][4] = {};
    warp_gemm3<4, 4>(Ah, Al, Bh, Bl, wm, wn, g, t, acc);
    __syncthreads();

#pragma unroll
    for (int mt = 0; mt < 4; mt++)
#pragma unroll
        for (int nt = 0; nt < 4; nt++) {
            int row = wm + mt * 16 + g;
            int col = wn + nt * 8 + 2 * t;
            float bb0 = b1[col], bb1 = b1[col + 1];
            float x0 = acc[mt][nt][0] + bb0, x1 = acc[mt][nt][1] + bb1;
            float x2 = acc[mt][nt][2] + bb0, x3 = acc[mt][nt][3] + bb1;
            float gl0 = 0.5f * x0 * (1.0f + erff(x0 * 0.70710678118654752f));
            float gl1 = 0.5f * x1 * (1.0f + erff(x1 * 0.70710678118654752f));
            float gl2 = 0.5f * x2 * (1.0f + erff(x2 * 0.70710678118654752f));
            float gl3 = 0.5f * x3 * (1.0f + erff(x3 * 0.70710678118654752f));
            uint32_t hi, lo;
            split2(gl0, gl1, hi, lo);
            *(uint32_t*)(Ah + row * SA + col) = hi;
            *(uint32_t*)(Al + row * SA + col) = lo;
            split2(gl2, gl3, hi, lo);
            *(uint32_t*)(Ah + (row + 8) * SA + col) = hi;
            *(uint32_t*)(Al + (row + 8) * SA + col) = lo;
        }
    copy_tile(g_w2h, g_w2l, Bh, Bl, tid, 512);
    __syncthreads();

    float acc2[4][4][4] = {};
    warp_gemm3<4, 4>(Ah, Al, Bh, Bl, wm, wn, g, t, acc2);

#pragma unroll
    for (int mt = 0; mt < 4; mt++)
#pragma unroll
        for (int nt = 0; nt < 4; nt++) {
            int row = row0 + wm + mt * 16 + g;
            int col = wn + nt * 8 + 2 * t;
            float bb0 = b2[col], bb1 = b2[col + 1];
            size_t g0 = (size_t)row * 128 + col;
            size_t g1 = (size_t)(row + 8) * 128 + col;
            float2 x0 = *(const float2*)(g_xacc + g0);
            float2 x1 = *(const float2*)(g_xacc + g1);
            float2 o0 = {x0.x + acc2[mt][nt][0] + bb0, x0.y + acc2[mt][nt][1] + bb1};
            float2 o1 = {x1.x + acc2[mt][nt][2] + bb0, x1.y + acc2[mt][nt][3] + bb1};
            *(float2*)(out + g0) = o0;
            *(float2*)(out + g1) = o1;
        }
}

// =====================================================================
// launch
// =====================================================================
extern "C" void kernel_launch(void* const* d_in, const int* in_sizes, int n_in,
                              void* d_out, int out_size) {
    const float* qz    = (const float*)d_in[0];
    const float* unary = (const float*)d_in[1];
    const float* tuw   = (const float*)d_in[2];
    const float* tvw   = (const float*)d_in[3];
    const float* cuw   = (const float*)d_in[4];
    const float* cvw   = (const float*)d_in[5];
    const float* topic = (const float*)d_in[6];
    const float* gamma = (const float*)d_in[7];
    const float* beta  = (const float*)d_in[8];
    const float* w1    = (const float*)d_in[9];
    const float* b1    = (const float*)d_in[10];
    const float* w2    = (const float*)d_in[11];
    const float* b2    = (const float*)d_in[12];
    float* out = (float*)d_out;

    const int SMG = 6 * TILE_U16 * 2;                   // 208896 (gemm4, mlp)
    const int SMA = 4 * TILE_U16 * 2 + 8192;            // 147456
    const int SMT = 6 * TILE_U16 * 2 + 512;             // 209408

    cudaFuncSetAttribute(k_gemm4, cudaFuncAttributeMaxDynamicSharedMemorySize, SMG);
    cudaFuncSetAttribute(k_time_attn, cudaFuncAttributeMaxDynamicSharedMemorySize, SMA);
    cudaFuncSetAttribute(k_chan_attn, cudaFuncAttributeMaxDynamicSharedMemorySize, SMA);
    cudaFuncSetAttribute(k_topic, cudaFuncAttributeMaxDynamicSharedMemorySize, SMT);
    cudaFuncSetAttribute(k_mlp, cudaFuncAttributeMaxDynamicSharedMemorySize, SMG);

    k_prep<<<512, 256>>>(tuw, tvw, cuw, cvw, topic, w1, w2);
    k_ln_init<<<NROW / 8, 256>>>(qz, unary, gamma, beta);
    k_gemm4<<<NROW / 256, 512, SMG>>>();
    k_time_attn<<<NB * NC, 512, SMA>>>();
    k_chan_attn<<<NB * NP, 512, SMA>>>();
    k_topic<<<NROW / 128, 512, SMT>>>();
    k_mlp<<<NROW / 256, 512, SMG>>>(gamma, beta, b1, b2, out);
}

// round 14
// speedup vs baseline: 1.1207x; 1.0603x over previous
#include <cuda_runtime.h>
#include <cuda_bf16.h>
#include <stdint.h>
#include <math.h>

#define NB 4
#define NC 128
#define NP 128
#define ND 128
#define NG 512
#define NROW (NB * NC * NP)            // 65536
#define NELEM ((size_t)NROW * ND)      // 8388608

typedef unsigned long long u64;

#define SA 136                         // bf16 stride for mma tiles
#define TILE_U16 (128 * SA)            // 17408 uint16 per tile
#define OFF32 (NROW * 64)              // u32 per split buffer

// -------------------- scratch --------------------
__device__ float g_qzn[NELEM];
__device__ float g_xacc[NELEM];

// packed bf16x2 (hi/lo split) buffers
__device__ uint32_t g_qh[OFF32], g_ql[OFF32];                  // qzn split
__device__ uint32_t g_sph[4 * OFF32], g_spl[4 * OFF32];        // tu/tv/cu/cv outputs split
__device__ uint32_t g_wh[4 * 4 * 8192], g_wl[4 * 4 * 8192];    // attention weights
__device__ uint32_t g_tnh[4 * 512 * 64], g_tnl[4 * 512 * 64];  // topic natural
__device__ uint32_t g_tth[4 * 4 * 8192], g_ttl[4 * 4 * 8192];  // topic transposed
__device__ uint32_t g_w1h[8192], g_w1l[8192];
__device__ uint32_t g_w2h[8192], g_w2l[8192];

// -------------------- helpers --------------------
__device__ __forceinline__ uint32_t pkbf(__nv_bfloat16 a, __nv_bfloat16 b) {
    return (uint32_t)__bfloat16_as_ushort(a) | ((uint32_t)__bfloat16_as_ushort(b) << 16);
}
__device__ __forceinline__ void split2(float x0, float x1, uint32_t &hi, uint32_t &lo) {
    __nv_bfloat16 h0 = __float2bfloat16(x0), h1 = __float2bfloat16(x1);
    hi = pkbf(h0, h1);
    lo = pkbf(__float2bfloat16(x0 - __bfloat162float(h0)),
              __float2bfloat16(x1 - __bfloat162float(h1)));
}

__device__ __forceinline__ void mma_bf16(float* c, const uint32_t* a, const uint32_t* b) {
    asm volatile(
        "mma.sync.aligned.m16n8k16.row.col.f32.bf16.bf16.f32 "
        "{%0,%1,%2,%3}, {%4,%5,%6,%7}, {%8,%9}, {%0,%1,%2,%3};"
        : "+f"(c[0]), "+f"(c[1]), "+f"(c[2]), "+f"(c[3])
        : "r"(a[0]), "r"(a[1]), "r"(a[2]), "r"(a[3]), "r"(b[0]), "r"(b[1]));
}

__device__ __forceinline__ void lda(const uint16_t* A, int r, int k, uint32_t* f) {
    const uint16_t* p = A + r * SA + k;
    f[0] = *(const uint32_t*)p;
    f[1] = *(const uint32_t*)(p + 8 * SA);
    f[2] = *(const uint32_t*)(p + 8);
    f[3] = *(const uint32_t*)(p + 8 * SA + 8);
}
__device__ __forceinline__ void ldb(const uint16_t* B, int n, int k, uint32_t* f) {
    const uint16_t* p = B + n * SA + k;
    f[0] = *(const uint32_t*)p;
    f[1] = *(const uint32_t*)(p + 8);
}

// copy packed-u32 contiguous global tile [rows][64] into smem u16 tile
template <int ROWS>
__device__ __forceinline__ void copy_tileN(const uint32_t* __restrict__ srch,
                                           const uint32_t* __restrict__ srcl,
                                           uint16_t* Ah, uint16_t* Al,
                                           int tid, int nthr) {
    const u64* sh = (const u64*)srch;
    const u64* sl = (const u64*)srcl;
    for (int i = tid; i < ROWS * 32; i += nthr) {
        int r = i >> 5, c4 = (i & 31) * 4;
        *(u64*)(Ah + r * SA + c4) = sh[i];
        *(u64*)(Al + r * SA + c4) = sl[i];
    }
}
#define copy_tile(sh, sl, Ah, Al, tid, nthr) copy_tileN<128>(sh, sl, Ah, Al, tid, nthr)

__device__ __forceinline__ void copy_tile_strided(const uint32_t* __restrict__ srch,
                                                  const uint32_t* __restrict__ srcl,
                                                  size_t row_base, int row_stride,
                                                  uint16_t* Ah, uint16_t* Al,
                                                  int tid, int nthr) {
    for (int i = tid; i < 4096; i += nthr) {
        int r = i >> 5, j = i & 31;
        size_t s = (row_base + (size_t)r * row_stride) * 32 + j;
        *(u64*)(Ah + r * SA + j * 4) = ((const u64*)srch)[s];
        *(u64*)(Al + r * SA + j * 4) = ((const u64*)srcl)[s];
    }
}

// 3-term warp GEMM
template <int MT, int NT>
__device__ __forceinline__ void warp_gemm3(
    const uint16_t* Ah, const uint16_t* Al,
    const uint16_t* Bh, const uint16_t* Bl,
    int wm, int wn, int g, int t, float (&acc)[MT][NT][4]) {
#pragma unroll
    for (int kt = 0; kt < 8; kt++) {
        int k = kt * 16 + 2 * t;
        uint32_t bh[NT][2], bl[NT][2];
#pragma unroll
        for (int nt = 0; nt < NT; nt++) {
            int n = wn + nt * 8 + g;
            ldb(Bh, n, k, bh[nt]);
            ldb(Bl, n, k, bl[nt]);
        }
#pragma unroll
        for (int mt = 0; mt < MT; mt++) {
            uint32_t ah[4], al[4];
            int r = wm + mt * 16 + g;
            lda(Ah, r, k, ah);
            lda(Al, r, k, al);
#pragma unroll
            for (int nt = 0; nt < NT; nt++) {
                mma_bf16(acc[mt][nt], ah, bh[nt]);
                mma_bf16(acc[mt][nt], ah, bl[nt]);
                mma_bf16(acc[mt][nt], al, bh[nt]);
            }
        }
    }
}

// =====================================================================
// K0: prep — split all static weights once.
// =====================================================================
__global__ __launch_bounds__(256) void k_prep(
    const float* __restrict__ tuw, const float* __restrict__ tvw,
    const float* __restrict__ cuw, const float* __restrict__ cvw,
    const float* __restrict__ topic,
    const float* __restrict__ w1, const float* __restrict__ w2) {
    int tid = blockIdx.x * 256 + threadIdx.x;
    int nth = gridDim.x * 256;
    for (int i = tid; i < 4 * 4 * 8192; i += nth) {
        int which = i >> 15;
        int rem = i & 32767;
        const float* W = (which == 0 ? tuw : which == 1 ? tvw : which == 2 ? cuw : cvw);
        float2 v = *(const float2*)(W + (size_t)rem * 2);
        uint32_t hi, lo; split2(v.x, v.y, hi, lo);
        g_wh[i] = hi; g_wl[i] = lo;
    }
    for (int i = tid; i < 4 * 512 * 64; i += nth) {
        float2 v = *(const float2*)(topic + (size_t)i * 2);
        uint32_t hi, lo; split2(v.x, v.y, hi, lo);
        g_tnh[i] = hi; g_tnl[i] = lo;
    }
    for (int i = tid; i < 4 * 4 * 8192; i += nth) {
        int b = i >> 15;
        int gc = (i >> 13) & 3;
        int d = (i >> 6) & 127;
        int g2 = i & 63;
        int grow = gc * 128 + g2 * 2;
        float x0 = topic[((size_t)b * 512 + grow) * 128 + d];
        float x1 = topic[((size_t)b * 512 + grow + 1) * 128 + d];
        uint32_t hi, lo; split2(x0, x1, hi, lo);
        g_tth[i] = hi; g_ttl[i] = lo;
    }
    for (int i = tid; i < 8192; i += nth) {
        float2 v = *(const float2*)(w1 + (size_t)i * 2);
        uint32_t hi, lo; split2(v.x, v.y, hi, lo);
        g_w1h[i] = hi; g_w1l[i] = lo;
        float2 u = *(const float2*)(w2 + (size_t)i * 2);
        split2(u.x, u.y, hi, lo);
        g_w2h[i] = hi; g_w2l[i] = lo;
    }
}

// =====================================================================
// K1: qzn = LN(qz) (fp32 + split); xacc = 0.5*(qz + unary).
// =====================================================================
__global__ __launch_bounds__(256) void k_ln_init(
    const float* __restrict__ qz, const float* __restrict__ unary,
    const float* __restrict__ gamma, const float* __restrict__ beta) {
    int row = blockIdx.x * 8 + (threadIdx.x >> 5);
    int lane = threadIdx.x & 31;
    size_t base = (size_t)row * 128 + lane * 4;
    float4 v = *(const float4*)(qz + base);
    float s = v.x + v.y + v.z + v.w;
    float ss = v.x * v.x + v.y * v.y + v.z * v.z + v.w * v.w;
#pragma unroll
    for (int o = 16; o > 0; o >>= 1) {
        s += __shfl_xor_sync(0xffffffffu, s, o);
        ss += __shfl_xor_sync(0xffffffffu, ss, o);
    }
    float m = s * (1.0f / 128.0f);
    float var = ss * (1.0f / 128.0f) - m * m;
    float inv = rsqrtf(var + 1e-5f);
    float4 u = *(const float4*)(unary + base);
    float4 g4 = *(const float4*)(gamma + lane * 4);
    float4 b4 = *(const float4*)(beta + lane * 4);
    float4 qn, xa;
    qn.x = (v.x - m) * inv * g4.x + b4.x;
    qn.y = (v.y - m) * inv * g4.y + b4.y;
    qn.z = (v.z - m) * inv * g4.z + b4.z;
    qn.w = (v.w - m) * inv * g4.w + b4.w;
    xa.x = 0.5f * (v.x + u.x);
    xa.y = 0.5f * (v.y + u.y);
    xa.z = 0.5f * (v.z + u.z);
    xa.w = 0.5f * (v.w + u.w);
    *(float4*)(g_qzn + base) = qn;
    *(float4*)(g_xacc + base) = xa;
    uint32_t hi, lo;
    split2(qn.x, qn.y, hi, lo);
    g_qh[row * 64 + lane * 2] = hi;
    g_ql[row * 64 + lane * 2] = lo;
    split2(qn.z, qn.w, hi, lo);
    g_qh[row * 64 + lane * 2 + 1] = hi;
    g_ql[row * 64 + lane * 2 + 1] = lo;
}

// =====================================================================
// gemm4 body: 256 rows, loop over 4 weights. 512 thr, m64n32.
// =====================================================================
__device__ __forceinline__ void gemm4_body(int bid, uint16_t* smu) {
    uint16_t* Ah = smu;                        // 256 rows
    uint16_t* Al = Ah + 2 * TILE_U16;
    uint16_t* Bh = Al + 2 * TILE_U16;          // 128 rows
    uint16_t* Bl = Bh + TILE_U16;
    int tid = threadIdx.x, lane = tid & 31, w = tid >> 5;
    int g = lane >> 2, t = lane & 3;
    int row0 = bid * 256;
    int b = row0 >> 14;
    int wm = (w >> 2) * 64, wn = (w & 3) * 32;

    copy_tileN<256>(g_qh + (size_t)row0 * 64, g_ql + (size_t)row0 * 64, Ah, Al, tid, 512);

    for (int which = 0; which < 4; which++) {
        int woff = which * 32768 + b * 8192;
        uint32_t* Oh = g_sph + (size_t)which * OFF32;
        uint32_t* Ol = g_spl + (size_t)which * OFF32;
        if (which > 0) __syncthreads();
        copy_tile(g_wh + woff, g_wl + woff, Bh, Bl, tid, 512);
        __syncthreads();

        float acc[4][4][4] = {};
        warp_gemm3<4, 4>(Ah, Al, Bh, Bl, wm, wn, g, t, acc);

#pragma unroll
        for (int mt = 0; mt < 4; mt++)
#pragma unroll
            for (int nt = 0; nt < 4; nt++) {
                int row = row0 + wm + mt * 16 + g;
                int col = wn + nt * 8 + 2 * t;
                uint32_t hi, lo;
                split2(acc[mt][nt][0], acc[mt][nt][1], hi, lo);
                Oh[(size_t)row * 64 + col / 2] = hi;
                Ol[(size_t)row * 64 + col / 2] = lo;
                split2(acc[mt][nt][2], acc[mt][nt][3], hi, lo);
                Oh[(size_t)(row + 8) * 64 + col / 2] = hi;
                Ol[(size_t)(row + 8) * 64 + col / 2] = lo;
            }
    }
}

// =====================================================================
// topic body (R13 exact): 128 rows, 512 thr, m32n32.
// =====================================================================
__device__ __forceinline__ void topic_body(int bid, uint16_t* smu) {
    uint16_t* Qh = smu;
    uint16_t* Ql = Qh + TILE_U16;
    uint16_t* Bh = Ql + TILE_U16;
    uint16_t* Bl = Bh + TILE_U16;
    uint16_t* Sh = Bl + TILE_U16;
    uint16_t* Sl = Sh + TILE_U16;
    float* rs = (float*)(Sl + TILE_U16);
    int tid = threadIdx.x, lane = tid & 31, w = tid >> 5;
    int g = lane >> 2, t = lane & 3;
    int wm = (w >> 2) * 32, wn = (w & 3) * 32;
    int row0 = bid * 128;
    int b = row0 >> 14;

    copy_tile(g_qh + (size_t)row0 * 64, g_ql + (size_t)row0 * 64, Qh, Ql, tid, 512);
    if (tid < 128) rs[tid] = 0.0f;

    float macc[2][4][4] = {};

    for (int gc = 0; gc < 4; gc++) {
        int noff = b * 32768 + gc * 8192;
        __syncthreads();
        copy_tile(g_tnh + noff, g_tnl + noff, Bh, Bl, tid, 512);
        __syncthreads();

        float sacc[2][4][4] = {};
        warp_gemm3<2, 4>(Qh, Ql, Bh, Bl, wm, wn, g, t, sacc);
        __syncthreads();

#pragma unroll
        for (int mt = 0; mt < 2; mt++) {
            int row = wm + mt * 16 + g;
            float p0 = 0.f, p1 = 0.f;
#pragma unroll
            for (int nt = 0; nt < 4; nt++) {
                float r0 = fmaxf(sacc[mt][nt][0], 0.f);
                float r1 = fmaxf(sacc[mt][nt][1], 0.f);
                float r2 = fmaxf(sacc[mt][nt][2], 0.f);
                float r3 = fmaxf(sacc[mt][nt][3], 0.f);
                p0 += r0 + r1;
                p1 += r2 + r3;
                int col = wn + nt * 8 + 2 * t;
                uint32_t hi, lo;
                split2(r0, r1, hi, lo);
                *(uint32_t*)(Sh + row * SA + col) = hi;
                *(uint32_t*)(Sl + row * SA + col) = lo;
                split2(r2, r3, hi, lo);
                *(uint32_t*)(Sh + (row + 8) * SA + col) = hi;
                *(uint32_t*)(Sl + (row + 8) * SA + col) = lo;
            }
            p0 += __shfl_xor_sync(0xffffffffu, p0, 1);
            p0 += __shfl_xor_sync(0xffffffffu, p0, 2);
            p1 += __shfl_xor_sync(0xffffffffu, p1, 1);
            p1 += __shfl_xor_sync(0xffffffffu, p1, 2);
            if (t == 0) {
                atomicAdd(rs + row, p0);
                atomicAdd(rs + row + 8, p1);
            }
        }
        copy_tile(g_tth + noff, g_ttl + noff, Bh, Bl, tid, 512);
        __syncthreads();

        warp_gemm3<2, 4>(Sh, Sl, Bh, Bl, wm, wn, g, t, macc);
    }
    __syncthreads();

#pragma unroll
    for (int mt = 0; mt < 2; mt++) {
        int row = wm + mt * 16 + g;
        float idn0 = 0.5f / fmaxf(rs[row], 1e-6f);
        float idn1 = 0.5f / fmaxf(rs[row + 8], 1e-6f);
#pragma unroll
        for (int nt = 0; nt < 4; nt++) {
            int col = wn + nt * 8 + 2 * t;
            size_t g0 = (size_t)(row0 + row) * 128 + col;
            size_t g1 = (size_t)(row0 + row + 8) * 128 + col;
            float2 x0 = *(float2*)(g_xacc + g0);
            float2 x1 = *(float2*)(g_xacc + g1);
            x0.x += macc[mt][nt][0] * idn0;
            x0.y += macc[mt][nt][1] * idn0;
            x1.x += macc[mt][nt][2] * idn1;
            x1.y += macc[mt][nt][3] * idn1;
            *(float2*)(g_xacc + g0) = x0;
            *(float2*)(g_xacc + g1) = x1;
        }
    }
}

// =====================================================================
// Fused K2: topic (blocks 0..511, longer) + gemm4 (blocks 512..767).
// No xacc race: gemm4 never touches xacc; nothing else runs.
// =====================================================================
__global__ __launch_bounds__(512) void k_topic_gemm4() {
    extern __shared__ uint16_t smu[];
    if (blockIdx.x < 512) topic_body(blockIdx.x, smu);
    else gemm4_body(blockIdx.x - 512, smu);
}

// =====================================================================
// attention score core (R9 exact).
// =====================================================================
__device__ __forceinline__ void attn_probs(const uint16_t* Uh, const uint16_t* Ul,
                                           const uint16_t* Vh, const uint16_t* Vl,
                                           float* sumbuf, int wp, int half,
                                           int g, int t, float (&probs)[8][4]) {
#pragma unroll
    for (int nt = 0; nt < 8; nt++)
#pragma unroll
        for (int c = 0; c < 4; c++) probs[nt][c] = 0.0f;

    int row0 = wp * 16 + g;
    for (int h = 0; h < 8; h++) {
        int k = h * 16 + 2 * t;
        uint32_t ah[4], al[4];
        lda(Uh, row0, k, ah);
        lda(Ul, row0, k, al);
        float sacc[8][4];
#pragma unroll
        for (int nt = 0; nt < 8; nt++) {
#pragma unroll
            for (int c = 0; c < 4; c++) sacc[nt][c] = 0.0f;
            int n = half * 64 + nt * 8 + g;
            uint32_t bh[2], bl[2];
            ldb(Vh, n, k, bh);
            ldb(Vl, n, k, bl);
            mma_bf16(sacc[nt], ah, bh);
            mma_bf16(sacc[nt], ah, bl);
            mma_bf16(sacc[nt], al, bh);
        }
        float s0 = 0.0f, s1 = 0.0f;
#pragma unroll
        for (int nt = 0; nt < 8; nt++) {
            sacc[nt][0] = __expf(0.25f * sacc[nt][0]);
            sacc[nt][1] = __expf(0.25f * sacc[nt][1]);
            sacc[nt][2] = __expf(0.25f * sacc[nt][2]);
            sacc[nt][3] = __expf(0.25f * sacc[nt][3]);
            s0 += sacc[nt][0] + sacc[nt][1];
            s1 += sacc[nt][2] + sacc[nt][3];
        }
        s0 += __shfl_xor_sync(0xffffffffu, s0, 1);
        s0 += __shfl_xor_sync(0xffffffffu, s0, 2);
        s1 += __shfl_xor_sync(0xffffffffu, s1, 1);
        s1 += __shfl_xor_sync(0xffffffffu, s1, 2);
        if (t == 0) {
            sumbuf[(h * 128 + row0) * 2 + half] = s0;
            sumbuf[(h * 128 + row0 + 8) * 2 + half] = s1;
        }
        __syncthreads();
        float inv0 = 1.0f / (16.0f * (sumbuf[(h * 128 + row0) * 2] +
                                      sumbuf[(h * 128 + row0) * 2 + 1]));
        float inv1 = 1.0f / (16.0f * (sumbuf[(h * 128 + row0 + 8) * 2] +
                                      sumbuf[(h * 128 + row0 + 8) * 2 + 1]));
#pragma unroll
        for (int nt = 0; nt < 8; nt++) {
            probs[nt][0] = fmaf(sacc[nt][0], inv0, probs[nt][0]);
            probs[nt][1] = fmaf(sacc[nt][1], inv0, probs[nt][1]);
            probs[nt][2] = fmaf(sacc[nt][2], inv1, probs[nt][2]);
            probs[nt][3] = fmaf(sacc[nt][3], inv1, probs[nt][3]);
        }
    }
}

// =====================================================================
// time attention body (R9 exact).
// =====================================================================
__device__ __forceinline__ void time_body(int bid, uint16_t* smu) {
    uint16_t* Uh = smu;
    uint16_t* Ul = Uh + TILE_U16;
    uint16_t* Vh = Ul + TILE_U16;
    uint16_t* Vl = Vh + TILE_U16;
    float* sumbuf = (float*)(Vl + TILE_U16);
    uint16_t* Qth = Uh;
    uint16_t* Qtl = Ul;
    float* qs = (float*)Vh;

    int tid = threadIdx.x, lane = tid & 31, w = tid >> 5;
    int g = lane >> 2, t = lane & 3;
    int wp = w & 7, half = w >> 3;
    size_t base = (size_t)bid * 16384;

    copy_tile(g_sph + (size_t)bid * 8192, g_spl + (size_t)bid * 8192, Uh, Ul, tid, 512);
    copy_tile(g_sph + OFF32 + (size_t)bid * 8192, g_spl + OFF32 + (size_t)bid * 8192,
              Vh, Vl, tid, 512);
    __syncthreads();

    float probs[8][4];
    attn_probs(Uh, Ul, Vh, Vl, sumbuf, wp, half, g, t, probs);
    __syncthreads();

    for (int i = tid; i < 16384; i += 512) {
        int q = i >> 7, d = i & 127;
        qs[q * 129 + d] = g_qzn[base + i];
    }
    __syncthreads();
    for (int i = tid; i < 8192; i += 512) {
        int d = i & 127, j = i >> 7;
        float x0 = qs[(2 * j) * 129 + d];
        float x1 = qs[(2 * j + 1) * 129 + d];
        uint32_t hi, lo; split2(x0, x1, hi, lo);
        *(uint32_t*)(Qth + d * SA + 2 * j) = hi;
        *(uint32_t*)(Qtl + d * SA + 2 * j) = lo;
    }
    __syncthreads();

    int prow = wp * 16 + g;
    for (int pass = 0; pass < 2; pass++) {
        float accp[8][4] = {};
#pragma unroll
        for (int kt = 0; kt < 4; kt++) {
            int k = half * 64 + kt * 16 + 2 * t;
            uint32_t ah[4], al[4];
            split2(probs[2 * kt][0], probs[2 * kt][1], ah[0], al[0]);
            split2(probs[2 * kt][2], probs[2 * kt][3], ah[1], al[1]);
            split2(probs[2 * kt + 1][0], probs[2 * kt + 1][1], ah[2], al[2]);
            split2(probs[2 * kt + 1][2], probs[2 * kt + 1][3], ah[3], al[3]);
#pragma unroll
            for (int nt = 0; nt < 8; nt++) {
                int n = pass * 64 + nt * 8 + g;
                uint32_t bh[2], bl[2];
                ldb(Qth, n, k, bh);
                ldb(Qtl, n, k, bl);
                mma_bf16(accp[nt], ah, bh);
                mma_bf16(accp[nt], ah, bl);
                mma_bf16(accp[nt], al, bh);
            }
        }
#pragma unroll
        for (int nt = 0; nt < 8; nt++) {
            int col = pass * 64 + nt * 8 + 2 * t;
            atomicAdd(&g_xacc[base + (size_t)prow * 128 + col], accp[nt][0]);
            atomicAdd(&g_xacc[base + (size_t)prow * 128 + col + 1], accp[nt][1]);
            atomicAdd(&g_xacc[base + (size_t)(prow + 8) * 128 + col], accp[nt][2]);
            atomicAdd(&g_xacc[base + (size_t)(prow + 8) * 128 + col + 1], accp[nt][3]);
        }
    }
}

// =====================================================================
// channel attention body (R9 logic; epilogue -> atomicAdd for fusion).
// =====================================================================
__device__ __forceinline__ void chan_body(int bid, uint16_t* smu) {
    uint16_t* Uh = smu;
    uint16_t* Ul = Uh + TILE_U16;
    uint16_t* Vh = Ul + TILE_U16;
    uint16_t* Vl = Vh + TILE_U16;
    float* sumbuf = (float*)(Vl + TILE_U16);

    int tid = threadIdx.x, lane = tid & 31, w = tid >> 5;
    int g = lane >> 2, t = lane & 3;
    int wp = w & 7, half = w >> 3;
    int b = bid >> 7, p = bid & 127;
    size_t rowbase = (size_t)b * 16384 + p;
    size_t bbase = (size_t)b * 2097152 + (size_t)p * 128;

    copy_tile_strided(g_sph + 2 * (size_t)OFF32, g_spl + 2 * (size_t)OFF32,
                      rowbase, 128, Uh, Ul, tid, 512);
    copy_tile_strided(g_sph + 3 * (size_t)OFF32, g_spl + 3 * (size_t)OFF32,
                      rowbase, 128, Vh, Vl, tid, 512);
    __syncthreads();

    float probs[8][4];
    attn_probs(Uh, Ul, Vh, Vl, sumbuf, wp, half, g, t, probs);

    int c0 = wp * 16 + g;
#pragma unroll
    for (int nt = 0; nt < 8; nt++) {
        int col = half * 64 + nt * 8 + 2 * t;
        size_t g0 = bbase + (size_t)c0 * 16384 + col;
        size_t g1 = bbase + (size_t)(c0 + 8) * 16384 + col;
        float2 q0 = *(const float2*)(g_qzn + g0);
        float2 q1 = *(const float2*)(g_qzn + g1);
        atomicAdd(&g_xacc[g0], probs[nt][0] * q0.x);
        atomicAdd(&g_xacc[g0 + 1], probs[nt][1] * q0.y);
        atomicAdd(&g_xacc[g1], probs[nt][2] * q1.x);
        atomicAdd(&g_xacc[g1 + 1], probs[nt][3] * q1.y);
    }
}

// =====================================================================
// Fused K3: time (blocks 0..511) + channel (blocks 512..1023).
// Both accumulate xacc via atomicAdd -> race-free.
// =====================================================================
__global__ __launch_bounds__(512) void k_attn() {
    extern __shared__ uint16_t smu[];
    if (blockIdx.x < 512) time_body(blockIdx.x, smu);
    else chan_body(blockIdx.x - 512, smu);
}

// =====================================================================
// K6 (mma): mlp. 256 rows/block, 512 thr, m64n32, grid 256. (R13 exact)
// =====================================================================
__global__ __launch_bounds__(512) void k_mlp(
    const float* __restrict__ gamma, const float* __restrict__ beta,
    const float* __restrict__ b1, const float* __restrict__ b2,
    float* __restrict__ out) {
    extern __shared__ uint16_t smu[];
    uint16_t* Ah = smu;
    uint16_t* Al = Ah + 2 * TILE_U16;
    uint16_t* Bh = Al + 2 * TILE_U16;
    uint16_t* Bl = Bh + TILE_U16;
    int tid = threadIdx.x, lane = tid & 31, w = tid >> 5;
    int g = lane >> 2, t = lane & 3;
    int row0 = blockIdx.x * 256;
    int wm = (w >> 2) * 64, wn = (w & 3) * 32;

    float4 g4 = *(const float4*)(gamma + lane * 4);
    float4 b4 = *(const float4*)(beta + lane * 4);
#pragma unroll
    for (int it = 0; it < 16; it++) {
        int r = w * 16 + it;
        size_t gb = (size_t)(row0 + r) * 128 + lane * 4;
        float4 v = *(const float4*)(g_xacc + gb);
        float s = v.x + v.y + v.z + v.w;
        float ss = v.x * v.x + v.y * v.y + v.z * v.z + v.w * v.w;
#pragma unroll
        for (int o = 16; o > 0; o >>= 1) {
            s += __shfl_xor_sync(0xffffffffu, s, o);
            ss += __shfl_xor_sync(0xffffffffu, ss, o);
        }
        float m = s * (1.0f / 128.0f);
        float var = ss * (1.0f / 128.0f) - m * m;
        float inv = rsqrtf(var + 1e-5f);
        float q0 = (v.x - m) * inv * g4.x + b4.x;
        float q1 = (v.y - m) * inv * g4.y + b4.y;
        float q2 = (v.z - m) * inv * g4.z + b4.z;
        float q3 = (v.w - m) * inv * g4.w + b4.w;
        uint32_t hi, lo;
        split2(q0, q1, hi, lo);
        *(uint32_t*)(Ah + r * SA + lane * 4) = hi;
        *(uint32_t*)(Al + r * SA + lane * 4) = lo;
        split2(q2, q3, hi, lo);
        *(uint32_t*)(Ah + r * SA + lane * 4 + 2) = hi;
        *(uint32_t*)(Al + r * SA + lane * 4 + 2) = lo;
    }
    copy_tile(g_w1h, g_w1l, Bh, Bl, tid, 512);
    __syncthreads();

    float acc[4][4][4] = {};
    warp_gemm3<4, 4>(Ah, Al, Bh, Bl, wm, wn, g, t, acc);
    __syncthreads();

#pragma unroll
    for (int mt = 0; mt < 4; mt++)
#pragma unroll
        for (int nt = 0; nt < 4; nt++) {
            int row = wm + mt * 16 + g;
            int col = wn + nt * 8 + 2 * t;
            float bb0 = b1[col], bb1 = b1[col + 1];
            float x0 = acc[mt][nt][0] + bb0, x1 = acc[mt][nt][1] + bb1;
            float x2 = acc[mt][nt][2] + bb0, x3 = acc[mt][nt][3] + bb1;
            float gl0 = 0.5f * x0 * (1.0f + erff(x0 * 0.70710678118654752f));
            float gl1 = 0.5f * x1 * (1.0f + erff(x1 * 0.70710678118654752f));
            float gl2 = 0.5f * x2 * (1.0f + erff(x2 * 0.70710678118654752f));
            float gl3 = 0.5f * x3 * (1.0f + erff(x3 * 0.70710678118654752f));
            uint32_t hi, lo;
            split2(gl0, gl1, hi, lo);
            *(uint32_t*)(Ah + row * SA + col) = hi;
            *(uint32_t*)(Al + row * SA + col) = lo;
            split2(gl2, gl3, hi, lo);
            *(uint32_t*)(Ah + (row + 8) * SA + col) = hi;
            *(uint32_t*)(Al + (row + 8) * SA + col) = lo;
        }
    copy_tile(g_w2h, g_w2l, Bh, Bl, tid, 512);
    __syncthreads();

    float acc2[4][4][4] = {};
    warp_gemm3<4, 4>(Ah, Al, Bh, Bl, wm, wn, g, t, acc2);

#pragma unroll
    for (int mt = 0; mt < 4; mt++)
#pragma unroll
        for (int nt = 0; nt < 4; nt++) {
            int row = row0 + wm + mt * 16 + g;
            int col = wn + nt * 8 + 2 * t;
            float bb0 = b2[col], bb1 = b2[col + 1];
            size_t g0 = (size_t)row * 128 + col;
            size_t g1 = (size_t)(row + 8) * 128 + col;
            float2 x0 = *(const float2*)(g_xacc + g0);
            float2 x1 = *(const float2*)(g_xacc + g1);
            float2 o0 = {x0.x + acc2[mt][nt][0] + bb0, x0.y + acc2[mt][nt][1] + bb1};
            float2 o1 = {x1.x + acc2[mt][nt][2] + bb0, x1.y + acc2[mt][nt][3] + bb1};
            *(float2*)(out + g0) = o0;
            *(float2*)(out + g1) = o1;
        }
}

// =====================================================================
// launch
// =====================================================================
extern "C" void kernel_launch(void* const* d_in, const int* in_sizes, int n_in,
                              void* d_out, int out_size) {
    const float* qz    = (const float*)d_in[0];
    const float* unary = (const float*)d_in[1];
    const float* tuw   = (const float*)d_in[2];
    const float* tvw   = (const float*)d_in[3];
    const float* cuw   = (const float*)d_in[4];
    const float* cvw   = (const float*)d_in[5];
    const float* topic = (const float*)d_in[6];
    const float* gamma = (const float*)d_in[7];
    const float* beta  = (const float*)d_in[8];
    const float* w1    = (const float*)d_in[9];
    const float* b1    = (const float*)d_in[10];
    const float* w2    = (const float*)d_in[11];
    const float* b2    = (const float*)d_in[12];
    float* out = (float*)d_out;

    const int SMF1 = 6 * TILE_U16 * 2 + 512;            // 209408 (topic+gemm4)
    const int SMA  = 4 * TILE_U16 * 2 + 8192;           // 147456 (attn)
    const int SMG  = 6 * TILE_U16 * 2;                  // 208896 (mlp)

    cudaFuncSetAttribute(k_topic_gemm4, cudaFuncAttributeMaxDynamicSharedMemorySize, SMF1);
    cudaFuncSetAttribute(k_attn, cudaFuncAttributeMaxDynamicSharedMemorySize, SMA);
    cudaFuncSetAttribute(k_mlp, cudaFuncAttributeMaxDynamicSharedMemorySize, SMG);

    k_prep<<<512, 256>>>(tuw, tvw, cuw, cvw, topic, w1, w2);
    k_ln_init<<<NROW / 8, 256>>>(qz, unary, gamma, beta);
    k_topic_gemm4<<<512 + 256, 512, SMF1>>>();
    k_attn<<<1024, 512, SMA>>>();
    k_mlp<<<NROW / 256, 512, SMG>>>(gamma, beta, b1, b2, out);
}

// round 15
// speedup vs baseline: 1.1260x; 1.0047x over previous
#include <cuda_runtime.h>
#include <cuda_bf16.h>
#include <stdint.h>
#include <math.h>

#define NB 4
#define NC 128
#define NP 128
#define ND 128
#define NG 512
#define NROW (NB * NC * NP)            // 65536
#define NELEM ((size_t)NROW * ND)      // 8388608

typedef unsigned long long u64;

#define SA 136                         // bf16 stride for mma tiles
#define TILE_U16 (128 * SA)            // 17408 uint16 per tile
#define OFF32 (NROW * 64)              // u32 per split buffer

// -------------------- scratch --------------------
__device__ float g_qzn[NELEM];
__device__ float g_xacc[NELEM];

// packed bf16x2 (hi/lo split) buffers
__device__ uint32_t g_qh[OFF32], g_ql[OFF32];                  // qzn split
__device__ uint32_t g_sph[4 * OFF32], g_spl[4 * OFF32];        // tu/tv/cu/cv outputs split
__device__ uint32_t g_wh[4 * 4 * 8192], g_wl[4 * 4 * 8192];    // attention weights
__device__ uint32_t g_tnh[4 * 512 * 64], g_tnl[4 * 512 * 64];  // topic natural
__device__ uint32_t g_tth[4 * 4 * 8192], g_ttl[4 * 4 * 8192];  // topic transposed
__device__ uint32_t g_w1h[8192], g_w1l[8192];
__device__ uint32_t g_w2h[8192], g_w2l[8192];

// -------------------- helpers --------------------
__device__ __forceinline__ uint32_t pkbf(__nv_bfloat16 a, __nv_bfloat16 b) {
    return (uint32_t)__bfloat16_as_ushort(a) | ((uint32_t)__bfloat16_as_ushort(b) << 16);
}
__device__ __forceinline__ void split2(float x0, float x1, uint32_t &hi, uint32_t &lo) {
    __nv_bfloat16 h0 = __float2bfloat16(x0), h1 = __float2bfloat16(x1);
    hi = pkbf(h0, h1);
    lo = pkbf(__float2bfloat16(x0 - __bfloat162float(h0)),
              __float2bfloat16(x1 - __bfloat162float(h1)));
}

__device__ __forceinline__ void mma_bf16(float* c, const uint32_t* a, const uint32_t* b) {
    asm volatile(
        "mma.sync.aligned.m16n8k16.row.col.f32.bf16.bf16.f32 "
        "{%0,%1,%2,%3}, {%4,%5,%6,%7}, {%8,%9}, {%0,%1,%2,%3};"
        : "+f"(c[0]), "+f"(c[1]), "+f"(c[2]), "+f"(c[3])
        : "r"(a[0]), "r"(a[1]), "r"(a[2]), "r"(a[3]), "r"(b[0]), "r"(b[1]));
}

__device__ __forceinline__ void lda(const uint16_t* A, int r, int k, uint32_t* f) {
    const uint16_t* p = A + r * SA + k;
    f[0] = *(const uint32_t*)p;
    f[1] = *(const uint32_t*)(p + 8 * SA);
    f[2] = *(const uint32_t*)(p + 8);
    f[3] = *(const uint32_t*)(p + 8 * SA + 8);
}
__device__ __forceinline__ void ldb(const uint16_t* B, int n, int k, uint32_t* f) {
    const uint16_t* p = B + n * SA + k;
    f[0] = *(const uint32_t*)p;
    f[1] = *(const uint32_t*)(p + 8);
}

// copy packed-u32 contiguous global tile [rows][64] into smem u16 tile
template <int ROWS>
__device__ __forceinline__ void copy_tileN(const uint32_t* __restrict__ srch,
                                           const uint32_t* __restrict__ srcl,
                                           uint16_t* Ah, uint16_t* Al,
                                           int tid, int nthr) {
    const u64* sh = (const u64*)srch;
    const u64* sl = (const u64*)srcl;
    for (int i = tid; i < ROWS * 32; i += nthr) {
        int r = i >> 5, c4 = (i & 31) * 4;
        *(u64*)(Ah + r * SA + c4) = sh[i];
        *(u64*)(Al + r * SA + c4) = sl[i];
    }
}
#define copy_tile(sh, sl, Ah, Al, tid, nthr) copy_tileN<128>(sh, sl, Ah, Al, tid, nthr)

__device__ __forceinline__ void copy_tile_strided(const uint32_t* __restrict__ srch,
                                                  const uint32_t* __restrict__ srcl,
                                                  size_t row_base, int row_stride,
                                                  uint16_t* Ah, uint16_t* Al,
                                                  int tid, int nthr) {
    for (int i = tid; i < 4096; i += nthr) {
        int r = i >> 5, j = i & 31;
        size_t s = (row_base + (size_t)r * row_stride) * 32 + j;
        *(u64*)(Ah + r * SA + j * 4) = ((const u64*)srch)[s];
        *(u64*)(Al + r * SA + j * 4) = ((const u64*)srcl)[s];
    }
}

// 3-term warp GEMM
template <int MT, int NT>
__device__ __forceinline__ void warp_gemm3(
    const uint16_t* Ah, const uint16_t* Al,
    const uint16_t* Bh, const uint16_t* Bl,
    int wm, int wn, int g, int t, float (&acc)[MT][NT][4]) {
#pragma unroll
    for (int kt = 0; kt < 8; kt++) {
        int k = kt * 16 + 2 * t;
        uint32_t bh[NT][2], bl[NT][2];
#pragma unroll
        for (int nt = 0; nt < NT; nt++) {
            int n = wn + nt * 8 + g;
            ldb(Bh, n, k, bh[nt]);
            ldb(Bl, n, k, bl[nt]);
        }
#pragma unroll
        for (int mt = 0; mt < MT; mt++) {
            uint32_t ah[4], al[4];
            int r = wm + mt * 16 + g;
            lda(Ah, r, k, ah);
            lda(Al, r, k, al);
#pragma unroll
            for (int nt = 0; nt < NT; nt++) {
                mma_bf16(acc[mt][nt], ah, bh[nt]);
                mma_bf16(acc[mt][nt], ah, bl[nt]);
                mma_bf16(acc[mt][nt], al, bh[nt]);
            }
        }
    }
}

// =====================================================================
// prep body: split all static weights once. (grid-strided over nth)
// =====================================================================
__device__ __forceinline__ void prep_body(
    int tid, int nth,
    const float* __restrict__ tuw, const float* __restrict__ tvw,
    const float* __restrict__ cuw, const float* __restrict__ cvw,
    const float* __restrict__ topic,
    const float* __restrict__ w1, const float* __restrict__ w2) {
    for (int i = tid; i < 4 * 4 * 8192; i += nth) {
        int which = i >> 15;
        int rem = i & 32767;
        const float* W = (which == 0 ? tuw : which == 1 ? tvw : which == 2 ? cuw : cvw);
        float2 v = *(const float2*)(W + (size_t)rem * 2);
        uint32_t hi, lo; split2(v.x, v.y, hi, lo);
        g_wh[i] = hi; g_wl[i] = lo;
    }
    for (int i = tid; i < 4 * 512 * 64; i += nth) {
        float2 v = *(const float2*)(topic + (size_t)i * 2);
        uint32_t hi, lo; split2(v.x, v.y, hi, lo);
        g_tnh[i] = hi; g_tnl[i] = lo;
    }
    for (int i = tid; i < 4 * 4 * 8192; i += nth) {
        int b = i >> 15;
        int gc = (i >> 13) & 3;
        int d = (i >> 6) & 127;
        int g2 = i & 63;
        int grow = gc * 128 + g2 * 2;
        float x0 = topic[((size_t)b * 512 + grow) * 128 + d];
        float x1 = topic[((size_t)b * 512 + grow + 1) * 128 + d];
        uint32_t hi, lo; split2(x0, x1, hi, lo);
        g_tth[i] = hi; g_ttl[i] = lo;
    }
    for (int i = tid; i < 8192; i += nth) {
        float2 v = *(const float2*)(w1 + (size_t)i * 2);
        uint32_t hi, lo; split2(v.x, v.y, hi, lo);
        g_w1h[i] = hi; g_w1l[i] = lo;
        float2 u = *(const float2*)(w2 + (size_t)i * 2);
        split2(u.x, u.y, hi, lo);
        g_w2h[i] = hi; g_w2l[i] = lo;
    }
}

// =====================================================================
// ln_init body: qzn = LN(qz) (fp32 + split); xacc = 0.5*(qz + unary).
// =====================================================================
__device__ __forceinline__ void ln_body(
    int bid, const float* __restrict__ qz, const float* __restrict__ unary,
    const float* __restrict__ gamma, const float* __restrict__ beta) {
    int row = bid * 8 + (threadIdx.x >> 5);
    int lane = threadIdx.x & 31;
    size_t base = (size_t)row * 128 + lane * 4;
    float4 v = *(const float4*)(qz + base);
    float s = v.x + v.y + v.z + v.w;
    float ss = v.x * v.x + v.y * v.y + v.z * v.z + v.w * v.w;
#pragma unroll
    for (int o = 16; o > 0; o >>= 1) {
        s += __shfl_xor_sync(0xffffffffu, s, o);
        ss += __shfl_xor_sync(0xffffffffu, ss, o);
    }
    float m = s * (1.0f / 128.0f);
    float var = ss * (1.0f / 128.0f) - m * m;
    float inv = rsqrtf(var + 1e-5f);
    float4 u = *(const float4*)(unary + base);
    float4 g4 = *(const float4*)(gamma + lane * 4);
    float4 b4 = *(const float4*)(beta + lane * 4);
    float4 qn, xa;
    qn.x = (v.x - m) * inv * g4.x + b4.x;
    qn.y = (v.y - m) * inv * g4.y + b4.y;
    qn.z = (v.z - m) * inv * g4.z + b4.z;
    qn.w = (v.w - m) * inv * g4.w + b4.w;
    xa.x = 0.5f * (v.x + u.x);
    xa.y = 0.5f * (v.y + u.y);
    xa.z = 0.5f * (v.z + u.z);
    xa.w = 0.5f * (v.w + u.w);
    *(float4*)(g_qzn + base) = qn;
    *(float4*)(g_xacc + base) = xa;
    uint32_t hi, lo;
    split2(qn.x, qn.y, hi, lo);
    g_qh[row * 64 + lane * 2] = hi;
    g_ql[row * 64 + lane * 2] = lo;
    split2(qn.z, qn.w, hi, lo);
    g_qh[row * 64 + lane * 2 + 1] = hi;
    g_ql[row * 64 + lane * 2 + 1] = lo;
}

// =====================================================================
// Fused K1: ln_init (blocks 0..8191) + prep (blocks 8192..8703).
// Independent inputs/outputs -> race-free.
// =====================================================================
__global__ __launch_bounds__(256) void k_prep_ln(
    const float* __restrict__ qz, const float* __restrict__ unary,
    const float* __restrict__ gamma, const float* __restrict__ beta,
    const float* __restrict__ tuw, const float* __restrict__ tvw,
    const float* __restrict__ cuw, const float* __restrict__ cvw,
    const float* __restrict__ topic,
    const float* __restrict__ w1, const float* __restrict__ w2) {
    if (blockIdx.x < 8192) {
        ln_body(blockIdx.x, qz, unary, gamma, beta);
    } else {
        int tid = (blockIdx.x - 8192) * 256 + threadIdx.x;
        prep_body(tid, 512 * 256, tuw, tvw, cuw, cvw, topic, w1, w2);
    }
}

// =====================================================================
// gemm4 body: 256 rows, loop over 4 weights. 512 thr, m64n32.
// =====================================================================
__device__ __forceinline__ void gemm4_body(int bid, uint16_t* smu) {
    uint16_t* Ah = smu;                        // 256 rows
    uint16_t* Al = Ah + 2 * TILE_U16;
    uint16_t* Bh = Al + 2 * TILE_U16;          // 128 rows
    uint16_t* Bl = Bh + TILE_U16;
    int tid = threadIdx.x, lane = tid & 31, w = tid >> 5;
    int g = lane >> 2, t = lane & 3;
    int row0 = bid * 256;
    int b = row0 >> 14;
    int wm = (w >> 2) * 64, wn = (w & 3) * 32;

    copy_tileN<256>(g_qh + (size_t)row0 * 64, g_ql + (size_t)row0 * 64, Ah, Al, tid, 512);

    for (int which = 0; which < 4; which++) {
        int woff = which * 32768 + b * 8192;
        uint32_t* Oh = g_sph + (size_t)which * OFF32;
        uint32_t* Ol = g_spl + (size_t)which * OFF32;
        if (which > 0) __syncthreads();
        copy_tile(g_wh + woff, g_wl + woff, Bh, Bl, tid, 512);
        __syncthreads();

        float acc[4][4][4] = {};
        warp_gemm3<4, 4>(Ah, Al, Bh, Bl, wm, wn, g, t, acc);

#pragma unroll
        for (int mt = 0; mt < 4; mt++)
#pragma unroll
            for (int nt = 0; nt < 4; nt++) {
                int row = row0 + wm + mt * 16 + g;
                int col = wn + nt * 8 + 2 * t;
                uint32_t hi, lo;
                split2(acc[mt][nt][0], acc[mt][nt][1], hi, lo);
                Oh[(size_t)row * 64 + col / 2] = hi;
                Ol[(size_t)row * 64 + col / 2] = lo;
                split2(acc[mt][nt][2], acc[mt][nt][3], hi, lo);
                Oh[(size_t)(row + 8) * 64 + col / 2] = hi;
                Ol[(size_t)(row + 8) * 64 + col / 2] = lo;
            }
    }
}

// =====================================================================
// topic body (R13 exact): 128 rows, 512 thr, m32n32.
// =====================================================================
__device__ __forceinline__ void topic_body(int bid, uint16_t* smu) {
    uint16_t* Qh = smu;
    uint16_t* Ql = Qh + TILE_U16;
    uint16_t* Bh = Ql + TILE_U16;
    uint16_t* Bl = Bh + TILE_U16;
    uint16_t* Sh = Bl + TILE_U16;
    uint16_t* Sl = Sh + TILE_U16;
    float* rs = (float*)(Sl + TILE_U16);
    int tid = threadIdx.x, lane = tid & 31, w = tid >> 5;
    int g = lane >> 2, t = lane & 3;
    int wm = (w >> 2) * 32, wn = (w & 3) * 32;
    int row0 = bid * 128;
    int b = row0 >> 14;

    copy_tile(g_qh + (size_t)row0 * 64, g_ql + (size_t)row0 * 64, Qh, Ql, tid, 512);
    if (tid < 128) rs[tid] = 0.0f;

    float macc[2][4][4] = {};

    for (int gc = 0; gc < 4; gc++) {
        int noff = b * 32768 + gc * 8192;
        __syncthreads();
        copy_tile(g_tnh + noff, g_tnl + noff, Bh, Bl, tid, 512);
        __syncthreads();

        float sacc[2][4][4] = {};
        warp_gemm3<2, 4>(Qh, Ql, Bh, Bl, wm, wn, g, t, sacc);
        __syncthreads();

#pragma unroll
        for (int mt = 0; mt < 2; mt++) {
            int row = wm + mt * 16 + g;
            float p0 = 0.f, p1 = 0.f;
#pragma unroll
            for (int nt = 0; nt < 4; nt++) {
                float r0 = fmaxf(sacc[mt][nt][0], 0.f);
                float r1 = fmaxf(sacc[mt][nt][1], 0.f);
                float r2 = fmaxf(sacc[mt][nt][2], 0.f);
                float r3 = fmaxf(sacc[mt][nt][3], 0.f);
                p0 += r0 + r1;
                p1 += r2 + r3;
                int col = wn + nt * 8 + 2 * t;
                uint32_t hi, lo;
                split2(r0, r1, hi, lo);
                *(uint32_t*)(Sh + row * SA + col) = hi;
                *(uint32_t*)(Sl + row * SA + col) = lo;
                split2(r2, r3, hi, lo);
                *(uint32_t*)(Sh + (row + 8) * SA + col) = hi;
                *(uint32_t*)(Sl + (row + 8) * SA + col) = lo;
            }
            p0 += __shfl_xor_sync(0xffffffffu, p0, 1);
            p0 += __shfl_xor_sync(0xffffffffu, p0, 2);
            p1 += __shfl_xor_sync(0xffffffffu, p1, 1);
            p1 += __shfl_xor_sync(0xffffffffu, p1, 2);
            if (t == 0) {
                atomicAdd(rs + row, p0);
                atomicAdd(rs + row + 8, p1);
            }
        }
        copy_tile(g_tth + noff, g_ttl + noff, Bh, Bl, tid, 512);
        __syncthreads();

        warp_gemm3<2, 4>(Sh, Sl, Bh, Bl, wm, wn, g, t, macc);
    }
    __syncthreads();

#pragma unroll
    for (int mt = 0; mt < 2; mt++) {
        int row = wm + mt * 16 + g;
        float idn0 = 0.5f / fmaxf(rs[row], 1e-6f);
        float idn1 = 0.5f / fmaxf(rs[row + 8], 1e-6f);
#pragma unroll
        for (int nt = 0; nt < 4; nt++) {
            int col = wn + nt * 8 + 2 * t;
            size_t g0 = (size_t)(row0 + row) * 128 + col;
            size_t g1 = (size_t)(row0 + row + 8) * 128 + col;
            float2 x0 = *(float2*)(g_xacc + g0);
            float2 x1 = *(float2*)(g_xacc + g1);
            x0.x += macc[mt][nt][0] * idn0;
            x0.y += macc[mt][nt][1] * idn0;
            x1.x += macc[mt][nt][2] * idn1;
            x1.y += macc[mt][nt][3] * idn1;
            *(float2*)(g_xacc + g0) = x0;
            *(float2*)(g_xacc + g1) = x1;
        }
    }
}

// =====================================================================
// Fused K2: topic (blocks 0..511, longer) + gemm4 (blocks 512..767).
// =====================================================================
__global__ __launch_bounds__(512) void k_topic_gemm4() {
    extern __shared__ uint16_t smu[];
    if (blockIdx.x < 512) topic_body(blockIdx.x, smu);
    else gemm4_body(blockIdx.x - 512, smu);
}

// =====================================================================
// attention score core (R9 exact).
// =====================================================================
__device__ __forceinline__ void attn_probs(const uint16_t* Uh, const uint16_t* Ul,
                                           const uint16_t* Vh, const uint16_t* Vl,
                                           float* sumbuf, int wp, int half,
                                           int g, int t, float (&probs)[8][4]) {
#pragma unroll
    for (int nt = 0; nt < 8; nt++)
#pragma unroll
        for (int c = 0; c < 4; c++) probs[nt][c] = 0.0f;

    int row0 = wp * 16 + g;
    for (int h = 0; h < 8; h++) {
        int k = h * 16 + 2 * t;
        uint32_t ah[4], al[4];
        lda(Uh, row0, k, ah);
        lda(Ul, row0, k, al);
        float sacc[8][4];
#pragma unroll
        for (int nt = 0; nt < 8; nt++) {
#pragma unroll
            for (int c = 0; c < 4; c++) sacc[nt][c] = 0.0f;
            int n = half * 64 + nt * 8 + g;
            uint32_t bh[2], bl[2];
            ldb(Vh, n, k, bh);
            ldb(Vl, n, k, bl);
            mma_bf16(sacc[nt], ah, bh);
            mma_bf16(sacc[nt], ah, bl);
            mma_bf16(sacc[nt], al, bh);
        }
        float s0 = 0.0f, s1 = 0.0f;
#pragma unroll
        for (int nt = 0; nt < 8; nt++) {
            sacc[nt][0] = __expf(0.25f * sacc[nt][0]);
            sacc[nt][1] = __expf(0.25f * sacc[nt][1]);
            sacc[nt][2] = __expf(0.25f * sacc[nt][2]);
            sacc[nt][3] = __expf(0.25f * sacc[nt][3]);
            s0 += sacc[nt][0] + sacc[nt][1];
            s1 += sacc[nt][2] + sacc[nt][3];
        }
        s0 += __shfl_xor_sync(0xffffffffu, s0, 1);
        s0 += __shfl_xor_sync(0xffffffffu, s0, 2);
        s1 += __shfl_xor_sync(0xffffffffu, s1, 1);
        s1 += __shfl_xor_sync(0xffffffffu, s1, 2);
        if (t == 0) {
            sumbuf[(h * 128 + row0) * 2 + half] = s0;
            sumbuf[(h * 128 + row0 + 8) * 2 + half] = s1;
        }
        __syncthreads();
        float inv0 = 1.0f / (16.0f * (sumbuf[(h * 128 + row0) * 2] +
                                      sumbuf[(h * 128 + row0) * 2 + 1]));
        float inv1 = 1.0f / (16.0f * (sumbuf[(h * 128 + row0 + 8) * 2] +
                                      sumbuf[(h * 128 + row0 + 8) * 2 + 1]));
#pragma unroll
        for (int nt = 0; nt < 8; nt++) {
            probs[nt][0] = fmaf(sacc[nt][0], inv0, probs[nt][0]);
            probs[nt][1] = fmaf(sacc[nt][1], inv0, probs[nt][1]);
            probs[nt][2] = fmaf(sacc[nt][2], inv1, probs[nt][2]);
            probs[nt][3] = fmaf(sacc[nt][3], inv1, probs[nt][3]);
        }
    }
}

// =====================================================================
// time attention body (R9 exact).
// =====================================================================
__device__ __forceinline__ void time_body(int bid, uint16_t* smu) {
    uint16_t* Uh = smu;
    uint16_t* Ul = Uh + TILE_U16;
    uint16_t* Vh = Ul + TILE_U16;
    uint16_t* Vl = Vh + TILE_U16;
    float* sumbuf = (float*)(Vl + TILE_U16);
    uint16_t* Qth = Uh;
    uint16_t* Qtl = Ul;
    float* qs = (float*)Vh;

    int tid = threadIdx.x, lane = tid & 31, w = tid >> 5;
    int g = lane >> 2, t = lane & 3;
    int wp = w & 7, half = w >> 3;
    size_t base = (size_t)bid * 16384;

    copy_tile(g_sph + (size_t)bid * 8192, g_spl + (size_t)bid * 8192, Uh, Ul, tid, 512);
    copy_tile(g_sph + OFF32 + (size_t)bid * 8192, g_spl + OFF32 + (size_t)bid * 8192,
              Vh, Vl, tid, 512);
    __syncthreads();

    float probs[8][4];
    attn_probs(Uh, Ul, Vh, Vl, sumbuf, wp, half, g, t, probs);
    __syncthreads();

    for (int i = tid; i < 16384; i += 512) {
        int q = i >> 7, d = i & 127;
        qs[q * 129 + d] = g_qzn[base + i];
    }
    __syncthreads();
    for (int i = tid; i < 8192; i += 512) {
        int d = i & 127, j = i >> 7;
        float x0 = qs[(2 * j) * 129 + d];
        float x1 = qs[(2 * j + 1) * 129 + d];
        uint32_t hi, lo; split2(x0, x1, hi, lo);
        *(uint32_t*)(Qth + d * SA + 2 * j) = hi;
        *(uint32_t*)(Qtl + d * SA + 2 * j) = lo;
    }
    __syncthreads();

    int prow = wp * 16 + g;
    for (int pass = 0; pass < 2; pass++) {
        float accp[8][4] = {};
#pragma unroll
        for (int kt = 0; kt < 4; kt++) {
            int k = half * 64 + kt * 16 + 2 * t;
            uint32_t ah[4], al[4];
            split2(probs[2 * kt][0], probs[2 * kt][1], ah[0], al[0]);
            split2(probs[2 * kt][2], probs[2 * kt][3], ah[1], al[1]);
            split2(probs[2 * kt + 1][0], probs[2 * kt + 1][1], ah[2], al[2]);
            split2(probs[2 * kt + 1][2], probs[2 * kt + 1][3], ah[3], al[3]);
#pragma unroll
            for (int nt = 0; nt < 8; nt++) {
                int n = pass * 64 + nt * 8 + g;
                uint32_t bh[2], bl[2];
                ldb(Qth, n, k, bh);
                ldb(Qtl, n, k, bl);
                mma_bf16(accp[nt], ah, bh);
                mma_bf16(accp[nt], ah, bl);
                mma_bf16(accp[nt], al, bh);
            }
        }
#pragma unroll
        for (int nt = 0; nt < 8; nt++) {
            int col = pass * 64 + nt * 8 + 2 * t;
            atomicAdd(&g_xacc[base + (size_t)prow * 128 + col], accp[nt][0]);
            atomicAdd(&g_xacc[base + (size_t)prow * 128 + col + 1], accp[nt][1]);
            atomicAdd(&g_xacc[base + (size_t)(prow + 8) * 128 + col], accp[nt][2]);
            atomicAdd(&g_xacc[base + (size_t)(prow + 8) * 128 + col + 1], accp[nt][3]);
        }
    }
}

// =====================================================================
// channel attention body (R14 exact).
// =====================================================================
__device__ __forceinline__ void chan_body(int bid, uint16_t* smu) {
    uint16_t* Uh = smu;
    uint16_t* Ul = Uh + TILE_U16;
    uint16_t* Vh = Ul + TILE_U16;
    uint16_t* Vl = Vh + TILE_U16;
    float* sumbuf = (float*)(Vl + TILE_U16);

    int tid = threadIdx.x, lane = tid & 31, w = tid >> 5;
    int g = lane >> 2, t = lane & 3;
    int wp = w & 7, half = w >> 3;
    int b = bid >> 7, p = bid & 127;
    size_t rowbase = (size_t)b * 16384 + p;
    size_t bbase = (size_t)b * 2097152 + (size_t)p * 128;

    copy_tile_strided(g_sph + 2 * (size_t)OFF32, g_spl + 2 * (size_t)OFF32,
                      rowbase, 128, Uh, Ul, tid, 512);
    copy_tile_strided(g_sph + 3 * (size_t)OFF32, g_spl + 3 * (size_t)OFF32,
                      rowbase, 128, Vh, Vl, tid, 512);
    __syncthreads();

    float probs[8][4];
    attn_probs(Uh, Ul, Vh, Vl, sumbuf, wp, half, g, t, probs);

    int c0 = wp * 16 + g;
#pragma unroll
    for (int nt = 0; nt < 8; nt++) {
        int col = half * 64 + nt * 8 + 2 * t;
        size_t g0 = bbase + (size_t)c0 * 16384 + col;
        size_t g1 = bbase + (size_t)(c0 + 8) * 16384 + col;
        float2 q0 = *(const float2*)(g_qzn + g0);
        float2 q1 = *(const float2*)(g_qzn + g1);
        atomicAdd(&g_xacc[g0], probs[nt][0] * q0.x);
        atomicAdd(&g_xacc[g0 + 1], probs[nt][1] * q0.y);
        atomicAdd(&g_xacc[g1], probs[nt][2] * q1.x);
        atomicAdd(&g_xacc[g1 + 1], probs[nt][3] * q1.y);
    }
}

// =====================================================================
// Fused K3: time (blocks 0..511) + channel (blocks 512..1023).
// =====================================================================
__global__ __launch_bounds__(512) void k_attn() {
    extern __shared__ uint16_t smu[];
    if (blockIdx.x < 512) time_body(blockIdx.x, smu);
    else chan_body(blockIdx.x - 512, smu);
}

// =====================================================================
// K6 (mma): mlp. 256 rows/block, 512 thr, m64n32, grid 256. (R13 exact)
// =====================================================================
__global__ __launch_bounds__(512) void k_mlp(
    const float* __restrict__ gamma, const float* __restrict__ beta,
    const float* __restrict__ b1, const float* __restrict__ b2,
    float* __restrict__ out) {
    extern __shared__ uint16_t smu[];
    uint16_t* Ah = smu;
    uint16_t* Al = Ah + 2 * TILE_U16;
    uint16_t* Bh = Al + 2 * TILE_U16;
    uint16_t* Bl = Bh + TILE_U16;
    int tid = threadIdx.x, lane = tid & 31, w = tid >> 5;
    int g = lane >> 2, t = lane & 3;
    int row0 = blockIdx.x * 256;
    int wm = (w >> 2) * 64, wn = (w & 3) * 32;

    float4 g4 = *(const float4*)(gamma + lane * 4);
    float4 b4 = *(const float4*)(beta + lane * 4);
#pragma unroll
    for (int it = 0; it < 16; it++) {
        int r = w * 16 + it;
        size_t gb = (size_t)(row0 + r) * 128 + lane * 4;
        float4 v = *(const float4*)(g_xacc + gb);
        float s = v.x + v.y + v.z + v.w;
        float ss = v.x * v.x + v.y * v.y + v.z * v.z + v.w * v.w;
#pragma unroll
        for (int o = 16; o > 0; o >>= 1) {
            s += __shfl_xor_sync(0xffffffffu, s, o);
            ss += __shfl_xor_sync(0xffffffffu, ss, o);
        }
        float m = s * (1.0f / 128.0f);
        float var = ss * (1.0f / 128.0f) - m * m;
        float inv = rsqrtf(var + 1e-5f);
        float q0 = (v.x - m) * inv * g4.x + b4.x;
        float q1 = (v.y - m) * inv * g4.y + b4.y;
        float q2 = (v.z - m) * inv * g4.z + b4.z;
        float q3 = (v.w - m) * inv * g4.w + b4.w;
        uint32_t hi, lo;
        split2(q0, q1, hi, lo);
        *(uint32_t*)(Ah + r * SA + lane * 4) = hi;
        *(uint32_t*)(Al + r * SA + lane * 4) = lo;
        split2(q2, q3, hi, lo);
        *(uint32_t*)(Ah + r * SA + lane * 4 + 2) = hi;
        *(uint32_t*)(Al + r * SA + lane * 4 + 2) = lo;
    }
    copy_tile(g_w1h, g_w1l, Bh, Bl, tid, 512);
    __syncthreads();

    float acc[4][4][4] = {};
    warp_gemm3<4, 4>(Ah, Al, Bh, Bl, wm, wn, g, t, acc);
    __syncthreads();

#pragma unroll
    for (int mt = 0; mt < 4; mt++)
#pragma unroll
        for (int nt = 0; nt < 4; nt++) {
            int row = wm + mt * 16 + g;
            int col = wn + nt * 8 + 2 * t;
            float bb0 = b1[col], bb1 = b1[col + 1];
            float x0 = acc[mt][nt][0] + bb0, x1 = acc[mt][nt][1] + bb1;
            float x2 = acc[mt][nt][2] + bb0, x3 = acc[mt][nt][3] + bb1;
            float gl0 = 0.5f * x0 * (1.0f + erff(x0 * 0.70710678118654752f));
            float gl1 = 0.5f * x1 * (1.0f + erff(x1 * 0.70710678118654752f));
            float gl2 = 0.5f * x2 * (1.0f + erff(x2 * 0.70710678118654752f));
            float gl3 = 0.5f * x3 * (1.0f + erff(x3 * 0.70710678118654752f));
            uint32_t hi, lo;
            split2(gl0, gl1, hi, lo);
            *(uint32_t*)(Ah + row * SA + col) = hi;
            *(uint32_t*)(Al + row * SA + col) = lo;
            split2(gl2, gl3, hi, lo);
            *(uint32_t*)(Ah + (row + 8) * SA + col) = hi;
            *(uint32_t*)(Al + (row + 8) * SA + col) = lo;
        }
    copy_tile(g_w2h, g_w2l, Bh, Bl, tid, 512);
    __syncthreads();

    float acc2[4][4][4] = {};
    warp_gemm3<4, 4>(Ah, Al, Bh, Bl, wm, wn, g, t, acc2);

#pragma unroll
    for (int mt = 0; mt < 4; mt++)
#pragma unroll
        for (int nt = 0; nt < 4; nt++) {
            int row = row0 + wm + mt * 16 + g;
            int col = wn + nt * 8 + 2 * t;
            float bb0 = b2[col], bb1 = b2[col + 1];
            size_t g0 = (size_t)row * 128 + col;
            size_t g1 = (size_t)(row + 8) * 128 + col;
            float2 x0 = *(const float2*)(g_xacc + g0);
            float2 x1 = *(const float2*)(g_xacc + g1);
            float2 o0 = {x0.x + acc2[mt][nt][0] + bb0, x0.y + acc2[mt][nt][1] + bb1};
            float2 o1 = {x1.x + acc2[mt][nt][2] + bb0, x1.y + acc2[mt][nt][3] + bb1};
            *(float2*)(out + g0) = o0;
            *(float2*)(out + g1) = o1;
        }
}

// =====================================================================
// launch
// =====================================================================
extern "C" void kernel_launch(void* const* d_in, const int* in_sizes, int n_in,
                              void* d_out, int out_size) {
    const float* qz    = (const float*)d_in[0];
    const float* unary = (const float*)d_in[1];
    const float* tuw   = (const float*)d_in[2];
    const float* tvw   = (const float*)d_in[3];
    const float* cuw   = (const float*)d_in[4];
    const float* cvw   = (const float*)d_in[5];
    const float* topic = (const float*)d_in[6];
    const float* gamma = (const float*)d_in[7];
    const float* beta  = (const float*)d_in[8];
    const float* w1    = (const float*)d_in[9];
    const float* b1    = (const float*)d_in[10];
    const float* w2    = (const float*)d_in[11];
    const float* b2    = (const float*)d_in[12];
    float* out = (float*)d_out;

    const int SMF1 = 6 * TILE_U16 * 2 + 512;            // 209408 (topic+gemm4)
    const int SMA  = 4 * TILE_U16 * 2 + 8192;           // 147456 (attn)
    const int SMG  = 6 * TILE_U16 * 2;                  // 208896 (mlp)

    cudaFuncSetAttribute(k_topic_gemm4, cudaFuncAttributeMaxDynamicSharedMemorySize, SMF1);
    cudaFuncSetAttribute(k_attn, cudaFuncAttributeMaxDynamicSharedMemorySize, SMA);
    cudaFuncSetAttribute(k_mlp, cudaFuncAttributeMaxDynamicSharedMemorySize, SMG);

    k_prep_ln<<<8192 + 512, 256>>>(qz, unary, gamma, beta,
                                   tuw, tvw, cuw, cvw, topic, w1, w2);
    k_topic_gemm4<<<512 + 256, 512, SMF1>>>();
    k_attn<<<1024, 512, SMA>>>();
    k_mlp<<<NROW / 256, 512, SMG>>>(gamma, beta, b1, b2, out);
}